// round 12
// baseline (speedup 1.0000x reference)
#include <cuda_runtime.h>
#include <cuda_bf16.h>
#include <math.h>
#include <stdint.h>

// Problem constants (fixed by setup_inputs)
#define N_TE   20000
#define M_IND  1024
#define D_DIM  16
#define BS     64
#define NB     16
#define SW     20096          // 314*64 padded width
#define JITTER 1e-3f
#define EPSV   1e-9f
#define NBLK   120            // persistent grid
#define NC     40             // group C (factorization) CTAs
#define N_CBAR_FINAL 23       // C-group barriers before the shared final phase

typedef float Row[BS + 1];
#define FACT_SMEM (3 * BS * (BS + 1) * 4)
#define TSTRIDE 4160          // floats per tile buffer (Row-compatible)

// ---- PTX helpers (sm_100-safe: mma.sync / ldmatrix / cp.async) ------------
__device__ __forceinline__ uint32_t smem_to_u32(const void* p) {
    uint32_t a;
    asm("{ .reg .u64 t; cvta.to.shared.u64 t, %1; cvt.u32.u64 %0, t; }" : "=r"(a) : "l"(p));
    return a;
}
#define CPA(dst, src) \
    asm volatile("cp.async.cg.shared.global [%0], [%1], 16;" :: "r"(dst), "l"(src))
#define CPC() asm volatile("cp.async.commit_group;" ::: "memory")
#define CPW0() asm volatile("cp.async.wait_group 0;" ::: "memory")
#define CPW1() asm volatile("cp.async.wait_group 1;" ::: "memory")
#define LDSM4(R, addr) \
    asm volatile("ldmatrix.sync.aligned.m8n8.x4.shared.b16 {%0,%1,%2,%3}, [%4];" \
        : "=r"((R)[0]), "=r"((R)[1]), "=r"((R)[2]), "=r"((R)[3]) : "r"(addr))
#define MMA16816(acc, a, b0_, b1_) \
    asm volatile("mma.sync.aligned.m16n8k16.row.col.f32.bf16.bf16.f32 " \
        "{%0,%1,%2,%3}, {%4,%5,%6,%7}, {%8,%9}, {%0,%1,%2,%3};" \
        : "+f"((acc)[0]), "+f"((acc)[1]), "+f"((acc)[2]), "+f"((acc)[3]) \
        : "r"((a)[0]), "r"((a)[1]), "r"((a)[2]), "r"((a)[3]), "r"(b0_), "r"(b1_))

// ---- fast 2^y for y <= 0 (FMA pipe; avoids slow MUFU) ---------------------
__device__ __forceinline__ float fexp2n(float y) {
    y = fmaxf(y, -125.0f);
    float r = y + 12582912.0f;
    int n = __float_as_int(r) - 0x4B400000;
    float f = y - (r - 12582912.0f);
    float p = 1.540353e-4f;
    p = fmaf(p, f, 1.3333558e-3f);
    p = fmaf(p, f, 9.6181296e-3f);
    p = fmaf(p, f, 5.5504109e-2f);
    p = fmaf(p, f, 2.4022651e-1f);
    p = fmaf(p, f, 6.9314718e-1f);
    p = fmaf(p, f, 1.0f);
    return __int_as_float(__float_as_int(p) + (n << 23));
}
#define NEG_HALF_LOG2E (-0.72134752f)

// ---- scratch (allocation-free: __device__ globals) ------------------------
__device__ float g_L[M_IND * M_IND];
__device__ float g_W[M_IND * M_IND];
__device__ float g_Zd[NB * BS * BS];
__device__ float g_tmp[512 * 512];
__device__ float g_xs[M_IND * D_DIM];
__device__ float g_nm[M_IND];
__device__ float g_a1[M_IND];
__device__ float g_a2[M_IND];
__device__ float g_q[8 * SW];
__device__ float g_mm[8 * SW];
__device__ float g_vv[8 * SW];
__device__ __nv_bfloat16 g_Whi[M_IND * M_IND];
__device__ __nv_bfloat16 g_Wlo[M_IND * M_IND];
__device__ __nv_bfloat16 g_Shi[(size_t)SW * M_IND];
__device__ __nv_bfloat16 g_Slo[(size_t)SW * M_IND];
__device__ unsigned g_cnt = 0;
__device__ volatile unsigned g_epoch = 0;
__device__ unsigned g_ccnt = 0;
__device__ volatile unsigned g_cepoch = 0;
__device__ volatile unsigned g_pflag[NB];   // per-panel ready flags (monotonic)

// ---------------------------------------------------------------------------
__device__ __forceinline__ void bar_gen(unsigned* cnt, volatile unsigned* ep,
                                        unsigned n, unsigned& sense) {
    __syncthreads();
    if (threadIdx.x == 0) {
        unsigned target = sense + 1;
        __threadfence();
        if (atomicAdd(cnt, 1u) == n - 1) {
            atomicExch(cnt, 0u);
            __threadfence();
            *ep = target;
        } else {
            while (*ep < target) { }
            __threadfence();
        }
    }
    __syncthreads();
    sense += 1;
}

// ---------------------------------------------------------------------------
// Swizzled flat tile layout: element (r, c) at r*64 + ((c>>2 ^ r>>2)&15)*4 + (c&3)
// ---------------------------------------------------------------------------
__device__ __forceinline__ float4 ldT4(const float* S, int r, int cb) {
    return *(const float4*)&S[r * 64 + (((cb) ^ (r >> 2)) & 15) * 4];
}
__device__ __forceinline__ void stT1(float* S, int r, int c, float v) {
    S[r * 64 + ((((c) >> 2) ^ (r >> 2)) & 15) * 4 + ((c) & 3)] = v;
}
// Direct loader: buf[r][c] = src[r*stride + c] (coalesced global, swizzled store)
__device__ __forceinline__ void load_direct(float* buf, const float* src, int stride, int tid) {
    for (int e = tid; e < 1024; e += 256) {
        int r = e >> 4, cb = e & 15;
        *(float4*)&buf[r * 64 + ((cb ^ (r >> 2)) & 15) * 4] =
            *(const float4*)&src[(size_t)r * stride + cb * 4];
    }
}
// Transposed loader: buf[j][i] = src[i*stride + j]
__device__ __forceinline__ void load_trans(float* buf, const float* src, int stride, int tid) {
    for (int e = tid; e < 1024; e += 256) {
        int i = e >> 4, c4 = (e & 15) * 4;
        float4 v = *(const float4*)&src[(size_t)i * stride + c4];
        stT1(buf, c4 + 0, i, v.x);
        stT1(buf, c4 + 1, i, v.y);
        stT1(buf, c4 + 2, i, v.z);
        stT1(buf, c4 + 3, i, v.w);
    }
}
// 64x64x64 micro: acc (+/-)= sum_c A[ty4+ii][c] * B[tx4+jj][c]
template <bool SUB>
__device__ __forceinline__ void mm64(const float* A, const float* B,
                                     float (&acc)[4][4], int ty4, int tx4) {
#pragma unroll
    for (int cb = 0; cb < 16; cb++) {
        float4 a[4], b[4];
#pragma unroll
        for (int ii = 0; ii < 4; ii++) a[ii] = ldT4(A, ty4 + ii, cb);
#pragma unroll
        for (int jj = 0; jj < 4; jj++) b[jj] = ldT4(B, tx4 + jj, cb);
#pragma unroll
        for (int ii = 0; ii < 4; ii++)
#pragma unroll
            for (int jj = 0; jj < 4; jj++) {
                if (SUB) {
                    acc[ii][jj] = fmaf(-a[ii].x, b[jj].x, acc[ii][jj]);
                    acc[ii][jj] = fmaf(-a[ii].y, b[jj].y, acc[ii][jj]);
                    acc[ii][jj] = fmaf(-a[ii].z, b[jj].z, acc[ii][jj]);
                    acc[ii][jj] = fmaf(-a[ii].w, b[jj].w, acc[ii][jj]);
                } else {
                    acc[ii][jj] = fmaf(a[ii].x, b[jj].x, acc[ii][jj]);
                    acc[ii][jj] = fmaf(a[ii].y, b[jj].y, acc[ii][jj]);
                    acc[ii][jj] = fmaf(a[ii].z, b[jj].z, acc[ii][jj]);
                    acc[ii][jj] = fmaf(a[ii].w, b[jj].w, acc[ii][jj]);
                }
            }
    }
}

// ---------------------------------------------------------------------------
// 64x64 Cholesky factor + inverse (Row layout). -> g_Zd + W diag.
// ---------------------------------------------------------------------------
__device__ void factor_inverse(Row* Lb, Row* Zb, int kout) {
    __shared__ float Mtmp[7 * 64];
    int tid = threadIdx.x, tx = tid % 16, ty = tid / 16;

    for (int e = tid; e < BS * BS; e += 256)
        Zb[e / BS][e % BS] = 0.f;
    __syncthreads();

    for (int j = 0; j < BS - 1; j++) {
        float inv = 1.f / Lb[j][j];
        for (int r = j + 1 + ty; r < BS; r += 16) {
            float lrj = Lb[r][j] * inv;
            for (int c = j + 1 + tx; c <= r; c += 16)
                Lb[r][c] -= lrj * Lb[c][j];
        }
        __syncthreads();
    }
    float vals[16];
    int q = 0;
    for (int e = tid; e < BS * BS; e += 256, q++) {
        int r = e / BS, c = e % BS;
        float v = Lb[r][c];
        if (c < r)       v *= rsqrtf(Lb[c][c]);
        else if (c == r) v = sqrtf(v);
        else             v = 0.f;
        vals[q] = v;
    }
    __syncthreads();
    q = 0;
    for (int e = tid; e < BS * BS; e += 256, q++)
        Lb[e / BS][e % BS] = vals[q];
    __syncthreads();

    if (tid < 64) {
        int g = tid >> 3, c = tid & 7, b0 = g * 8;
        Zb[b0 + c][b0 + c] = 1.f / Lb[b0 + c][b0 + c];
        for (int r = c + 1; r < 8; r++) {
            float s = 0.f;
            for (int k = c; k < r; k++)
                s += Lb[b0 + r][b0 + k] * Zb[b0 + k][b0 + c];
            Zb[b0 + r][b0 + c] = -s / Lb[b0 + r][b0 + r];
        }
    }
    __syncthreads();

    for (int bi = 1; bi < 8; bi++) {
        int tot = bi * 64;
        for (int e = tid; e < tot; e += 256) {
            int bj = e >> 6, rc = e & 63, r = rc >> 3, c = rc & 7;
            float s = 0.f;
            for (int k = bj * 8; k < bi * 8; k++)
                s += Lb[bi * 8 + r][k] * Zb[k][bj * 8 + c];
            Mtmp[e] = s;
        }
        __syncthreads();
        for (int e = tid; e < tot; e += 256) {
            int bj = e >> 6, rc = e & 63, r = rc >> 3, c = rc & 7;
            float s = 0.f;
#pragma unroll
            for (int t = 0; t < 8; t++)
                s += Zb[bi * 8 + r][bi * 8 + t] * Mtmp[bj * 64 + t * 8 + c];
            Zb[bi * 8 + r][bj * 8 + c] = -s;
        }
        __syncthreads();
    }

    for (int e = tid; e < BS * BS; e += 256) {
        int r = e / BS, c = e % BS;
        float v = Zb[r][c];
        g_Zd[kout * BS * BS + e] = v;
        g_W[(size_t)(kout * BS + r) * M_IND + kout * BS + c] = v;
    }
    __syncthreads();
}

// ---------------------------------------------------------------------------
// Shared final phase: bf16 split of W (mask unwritten upper) + a1/a2
// ---------------------------------------------------------------------------
__device__ void final_phase(const float* qu, const float* ch, int gthread, int tid) {
    for (int idx = gthread; idx < M_IND * M_IND; idx += NBLK * 256) {
        int r = idx >> 10, c = idx & 1023;
        float w = ((c >> 6) <= (r >> 6)) ? g_W[idx] : 0.f;
        __nv_bfloat16 h = __float2bfloat16(w);
        g_Whi[idx] = h;
        g_Wlo[idx] = __float2bfloat16(w - __bfloat162float(h));
    }
    int wid = gthread / 32, lane = tid % 32;
    for (int r = wid; r < M_IND; r += NBLK * 8) {
        float s1 = 0.f, s2 = 0.f;
        for (int c = lane; c <= r; c += 32) {
            float w = g_W[(size_t)r * M_IND + c];
            s1 += w * qu[c];
            s2 += w * ch[c];
        }
#pragma unroll
        for (int off = 16; off; off >>= 1) {
            s1 += __shfl_down_sync(0xffffffff, s1, off);
            s2 += __shfl_down_sync(0xffffffff, s2, off);
        }
        if (lane == 0) { g_a1[r] = s1; g_a2[r] = s2; }
    }
}

// ---------------------------------------------------------------------------
// Persistent kernel; group C (bid<NC): factorization; group S: Shi/Slo
// ---------------------------------------------------------------------------
__global__ void __launch_bounds__(256, 1) fact_kernel(const float* __restrict__ xm,
                                                      const float* __restrict__ qu,
                                                      const float* __restrict__ ch,
                                                      const float* __restrict__ ls,
                                                      const float* __restrict__ sv,
                                                      const float* __restrict__ Xte) {
    extern __shared__ __align__(16) float sm[];
    float* SA = sm;
    float* SB = sm + TSTRIDE;
    float* SC = sm + 2 * TSTRIDE;
    Row* SAr = (Row*)SA;
    Row* SBr = (Row*)SB;
    __shared__ unsigned sh_a, sh_c;
    int tid = threadIdx.x, bid = blockIdx.x;
    if (tid == 0) { sh_a = g_epoch; sh_c = g_cepoch; }
    __syncthreads();
    unsigned s_all = sh_a, s_c = sh_c;
    const unsigned basec = s_c;

    int gthread = bid * 256 + tid;
    int tx = tid % 16, ty = tid / 16;
    int tx4 = tx * 4, ty4 = ty * 4;
    float svv = fabsf(sv[0]);

    // phase 1 (all): pre-scaled xm rows + norms
    for (int m = gthread; m < M_IND; m += NBLK * 256) {
        float nrm = 0.f;
#pragma unroll
        for (int d = 0; d < D_DIM; d++) {
            float il = 1.f / (fabsf(ls[d]) + EPSV);
            float v = xm[m * D_DIM + d] * il;
            g_xs[m * D_DIM + d] = v;
            nrm += v * v;
        }
        g_nm[m] = nrm;
    }
    bar_gen(&g_cnt, &g_epoch, NBLK, s_all);

    if (bid >= NC) {
        // ================= group S: build Shi/Slo =================
        float* Xs = SA;
        float* Ms = SB;
        int ntile = (SW / 64) * (M_IND / 32);
        for (int x = bid - NC; x < ntile; x += NBLK - NC) {
            int n0 = (x % (SW / 64)) * 64, m0 = (x / (SW / 64)) * 32;
            for (int e = tid; e < 64 * D_DIM; e += 256) {
                int i = e / D_DIM, d = e % D_DIM;
                int n = n0 + i;
                float il = 1.f / (fabsf(ls[d]) + EPSV);
                Xs[i * 17 + d] = (n < N_TE) ? Xte[n * D_DIM + d] * il : 0.f;
            }
            for (int e = tid; e < 32 * D_DIM; e += 256) {
                int i = e / D_DIM, d = e % D_DIM;
                Ms[i * 17 + d] = g_xs[(m0 + i) * D_DIM + d];
            }
            __syncthreads();

            int sx = tid % 64, sy = tid / 64;
            int n = n0 + sx;
            __align__(16) __nv_bfloat16 h8[8];
            __align__(16) __nv_bfloat16 l8[8];
#pragma unroll
            for (int mi = 0; mi < 8; mi++) {
                int ml = sy * 8 + mi;
                float outv = 0.f;
                if (n < N_TE) {
                    float d2 = 0.f;
#pragma unroll
                    for (int d = 0; d < D_DIM; d++) {
                        float diff = Xs[sx * 17 + d] - Ms[ml * 17 + d];
                        d2 += diff * diff;
                    }
                    outv = svv * fexp2n(d2 * NEG_HALF_LOG2E);
                }
                __nv_bfloat16 h = __float2bfloat16(outv);
                h8[mi] = h;
                l8[mi] = __float2bfloat16(outv - __bfloat162float(h));
            }
            size_t off = (size_t)n * M_IND + m0 + sy * 8;
            *(uint4*)&g_Shi[off] = *(uint4*)h8;
            *(uint4*)&g_Slo[off] = *(uint4*)l8;
            __syncthreads();
        }
        if (tid == 0) {
            while (g_cepoch < basec + N_CBAR_FINAL) { }
            __threadfence();
        }
        __syncthreads();
        final_phase(qu, ch, gthread, tid);
        return;
    }

    // ================= group C: factorization =================
    // K_mm lower tiles (Row layout)
    for (int x = bid; x < NB * (NB + 1) / 2; x += NC) {
        int br = 0;
        while ((br + 1) * (br + 2) / 2 <= x) br++;
        int bc = x - br * (br + 1) / 2;
        for (int e = tid; e < 64 * D_DIM; e += 256) {
            int i = e >> 4, d = e & 15;
            SAr[i][d] = g_xs[(br * 64 + i) * D_DIM + d];
            SBr[i][d] = g_xs[(bc * 64 + i) * D_DIM + d];
        }
        if (tid < 64) {
            SAr[tid][16] = g_nm[br * 64 + tid];
            SBr[tid][16] = g_nm[bc * 64 + tid];
        }
        __syncthreads();
        float dot[4][4] = {};
#pragma unroll
        for (int d = 0; d < D_DIM; d++) {
            float av[4], bv[4];
#pragma unroll
            for (int ii = 0; ii < 4; ii++) av[ii] = SAr[ty4 + ii][d];
#pragma unroll
            for (int jj = 0; jj < 4; jj++) bv[jj] = SBr[tx4 + jj][d];
#pragma unroll
            for (int ii = 0; ii < 4; ii++)
#pragma unroll
                for (int jj = 0; jj < 4; jj++) dot[ii][jj] += av[ii] * bv[jj];
        }
#pragma unroll
        for (int ii = 0; ii < 4; ii++) {
            int gr = br * 64 + ty4 + ii;
            float nr = SAr[ty4 + ii][16];
#pragma unroll
            for (int jj = 0; jj < 4; jj++) {
                int gc = bc * 64 + tx4 + jj;
                float d2 = fmaxf(nr + SBr[tx4 + jj][16] - 2.f * dot[ii][jj], 0.f);
                float v = svv * fexp2n(d2 * NEG_HALF_LOG2E);
                if (gr == gc) v += JITTER;
                g_L[(size_t)gr * M_IND + gc] = v;
            }
        }
        __syncthreads();
    }
    if (bid == 0) {
        for (int e = tid; e < BS * BS; e += 256)
            SAr[e / BS][e % BS] = g_L[(size_t)(e / BS) * M_IND + (e % BS)];
        __syncthreads();
        factor_inverse(SAr, SBr, 0);
    }
    bar_gen(&g_ccnt, &g_cepoch, NC, s_c);                 // bar 1

    // Cholesky steps: ONE phase per step, flag-based panel->syrk dataflow
    for (int k = 0; k < NB - 1; k++) {
        int o = k * BS, t = NB - 1 - k;
        unsigned target = basec + (unsigned)(k + 1);

        if (bid == 0) {
            int bi = k + 1;
            load_direct(SA, &g_L[(size_t)(bi * BS) * M_IND + o], M_IND, tid);
            load_direct(SB, &g_Zd[k * BS * BS], BS, tid);
            __syncthreads();
            float acc[4][4] = {};
            mm64<false>(SA, SB, acc, ty4, tx4);
#pragma unroll
            for (int ii = 0; ii < 4; ii++) {
                *(float4*)&g_L[(size_t)(bi * BS + ty4 + ii) * M_IND + o + tx4] =
                    make_float4(acc[ii][0], acc[ii][1], acc[ii][2], acc[ii][3]);
                *(float4*)&SC[(ty4 + ii) * 64 + ((tx ^ ((ty4 + ii) >> 2)) & 15) * 4] =
                    make_float4(acc[ii][0], acc[ii][1], acc[ii][2], acc[ii][3]);
            }
            __threadfence();
            __syncthreads();
            if (tid == 0) g_pflag[bi] = target;
            // diag tile update with SC (P * P^T), then factor
            float u[4][4];
#pragma unroll
            for (int ii = 0; ii < 4; ii++) {
                float4 v = *(const float4*)&g_L[(size_t)(bi * BS + ty4 + ii) * M_IND + bi * BS + tx4];
                u[ii][0] = v.x; u[ii][1] = v.y; u[ii][2] = v.z; u[ii][3] = v.w;
            }
            mm64<true>(SC, SC, u, ty4, tx4);
            __syncthreads();
#pragma unroll
            for (int ii = 0; ii < 4; ii++)
#pragma unroll
                for (int jj = 0; jj < 4; jj++)
                    SAr[ty4 + ii][tx4 + jj] = u[ii][jj];
            factor_inverse(SAr, SBr, bi);
        } else {
            // panels bi = k+2 .. 15
            for (int p = bid - 1; p < t - 1; p += NC - 1) {
                int bi = k + 2 + p;
                load_direct(SA, &g_L[(size_t)(bi * BS) * M_IND + o], M_IND, tid);
                load_direct(SB, &g_Zd[k * BS * BS], BS, tid);
                __syncthreads();
                float acc[4][4] = {};
                mm64<false>(SA, SB, acc, ty4, tx4);
#pragma unroll
                for (int ii = 0; ii < 4; ii++)
                    *(float4*)&g_L[(size_t)(bi * BS + ty4 + ii) * M_IND + o + tx4] =
                        make_float4(acc[ii][0], acc[ii][1], acc[ii][2], acc[ii][3]);
                __threadfence();
                __syncthreads();
                if (tid == 0) g_pflag[bi] = target;
            }
            // syrk tiles
            int ntile = t * (t + 1) / 2;
            for (int x = bid; x < ntile; x += NC - 1) {
                int r = 0;
                while ((r + 1) * (r + 2) / 2 <= x) r++;
                int c = x - r * (r + 1) / 2;
                int bi = k + 1 + r, bj = k + 1 + c;
                if (tid == 0) {
                    while (g_pflag[bi] < target) { }
                    while (g_pflag[bj] < target) { }
                    __threadfence();
                }
                __syncthreads();
                load_direct(SA, &g_L[(size_t)(bi * BS) * M_IND + o], M_IND, tid);
                load_direct(SB, &g_L[(size_t)(bj * BS) * M_IND + o], M_IND, tid);
                __syncthreads();
                float u[4][4];
#pragma unroll
                for (int ii = 0; ii < 4; ii++) {
                    float4 v = *(const float4*)&g_L[(size_t)(bi * BS + ty4 + ii) * M_IND + bj * BS + tx4];
                    u[ii][0] = v.x; u[ii][1] = v.y; u[ii][2] = v.z; u[ii][3] = v.w;
                }
                mm64<true>(SA, SB, u, ty4, tx4);
#pragma unroll
                for (int ii = 0; ii < 4; ii++)
                    *(float4*)&g_L[(size_t)(bi * BS + ty4 + ii) * M_IND + bj * BS + tx4] =
                        make_float4(u[ii][0], u[ii][1], u[ii][2], u[ii][3]);
                __syncthreads();
            }
        }
        bar_gen(&g_ccnt, &g_cepoch, NC, s_c);             // bars 2..16
    }

    // doubling level 0: fused per pair (tmp transposed in SC)
    for (int p = bid; p < 8; p += NC) {
        int base = p * 128;
        load_direct(SA, &g_L[(size_t)(base + 64) * M_IND + base], M_IND, tid);   // L21
        load_trans(SB, &g_W[(size_t)base * M_IND + base], M_IND, tid);           // W11^T
        __syncthreads();
        float acc[4][4] = {};
        mm64<false>(SA, SB, acc, ty4, tx4);
        __syncthreads();
        // store tmp transposed: SC[j][i] = tmp[i][j]
#pragma unroll
        for (int ii = 0; ii < 4; ii++)
#pragma unroll
            for (int jj = 0; jj < 4; jj++)
                stT1(SC, tx4 + jj, ty4 + ii, acc[ii][jj]);
        __syncthreads();
        load_direct(SA, &g_W[(size_t)(base + 64) * M_IND + base + 64], M_IND, tid);  // W22
        __syncthreads();
        float ac2[4][4] = {};
        mm64<false>(SA, SC, ac2, ty4, tx4);
#pragma unroll
        for (int ii = 0; ii < 4; ii++)
            *(float4*)&g_W[(size_t)(base + 64 + ty4 + ii) * M_IND + base + tx4] =
                make_float4(-ac2[ii][0], -ac2[ii][1], -ac2[ii][2], -ac2[ii][3]);
        __syncthreads();
    }
    bar_gen(&g_ccnt, &g_cepoch, NC, s_c);                 // bar 17

    // doubling levels 1..3
    for (int l = 1; l < 4; l++) {
        int s = 64 << l, tt = 1 << l, pairs = 8 >> l;
        int tiles = pairs * tt * tt;

        for (int x = bid; x < tiles; x += NC) {
            int p = x / (tt * tt), rem = x % (tt * tt), tr = rem / tt, tc = rem % tt;
            int base = p * 2 * s;
            float acc[4][4] = {};
            for (int k0 = tc * BS; k0 < s; k0 += BS) {
                load_direct(SA, &g_L[(size_t)(base + s + tr * BS) * M_IND + base + k0], M_IND, tid);
                load_trans(SB, &g_W[(size_t)(base + k0) * M_IND + base + tc * BS], M_IND, tid);
                __syncthreads();
                mm64<false>(SA, SB, acc, ty4, tx4);
                __syncthreads();
            }
#pragma unroll
            for (int ii = 0; ii < 4; ii++)
                *(float4*)&g_tmp[(size_t)p * s * s + (tr * BS + ty4 + ii) * s + tc * BS + tx4] =
                    make_float4(acc[ii][0], acc[ii][1], acc[ii][2], acc[ii][3]);
            __syncthreads();
        }
        bar_gen(&g_ccnt, &g_cepoch, NC, s_c);             // bars 18,20,22

        for (int x = bid; x < tiles; x += NC) {
            int p = x / (tt * tt), rem = x % (tt * tt), tr = rem / tt, tc = rem % tt;
            int base = p * 2 * s;
            float acc[4][4] = {};
            for (int k0 = 0; k0 <= tr * BS; k0 += BS) {
                load_direct(SA, &g_W[(size_t)(base + s + tr * BS) * M_IND + base + s + k0], M_IND, tid);
                load_trans(SB, &g_tmp[(size_t)p * s * s + (size_t)k0 * s + tc * BS], s, tid);
                __syncthreads();
                mm64<false>(SA, SB, acc, ty4, tx4);
                __syncthreads();
            }
#pragma unroll
            for (int ii = 0; ii < 4; ii++)
                *(float4*)&g_W[(size_t)(base + s + tr * BS + ty4 + ii) * M_IND + base + tc * BS + tx4] =
                    make_float4(-acc[ii][0], -acc[ii][1], -acc[ii][2], -acc[ii][3]);
            __syncthreads();
        }
        bar_gen(&g_ccnt, &g_cepoch, NC, s_c);             // bars 19,21,23
    }

    final_phase(qu, ch, gthread, tid);
}

// ---------------------------------------------------------------------------
// Warp-MMA bf16 GEMM + fused epilogue (round-5/6 proven)
// ---------------------------------------------------------------------------
#define STG_BYTES 65536
__global__ void __launch_bounds__(256) gemm_tc() {
    extern __shared__ __align__(1024) char dsm[];
    __shared__ float Rq[8][32], Rm[8][32], Rv[8][32];
    __shared__ float a1s[128], a2s[128];

    const uint32_t sbase = smem_to_u32(dsm);
    int tid = threadIdx.x, wid = tid >> 5, lane = tid & 31;
    int n0 = blockIdx.x * 128;
    int mb = 7 - (int)blockIdx.y;
    int m0 = mb * 128;
    int nchunks = (m0 + 128) >> 6;

    if (tid < 128) { a1s[tid] = g_a1[m0 + tid]; a2s[tid] = g_a2[m0 + tid]; }

    int wm = (wid >> 2) * 64;
    int wn = (wid & 3) * 32;
    int lrow16 = lane & 15, lhalf = lane >> 4;

    float acc[4][4][4];
#pragma unroll
    for (int i = 0; i < 4; i++)
#pragma unroll
        for (int j = 0; j < 4; j++)
#pragma unroll
            for (int r = 0; r < 4; r++) acc[i][j][r] = 0.f;

    for (int c = 0; c < nchunks + 1; c++) {
        if (c < nchunks) {
            int k0 = c << 6;
            uint32_t buf = sbase + (uint32_t)(c & 1) * STG_BYTES;
#pragma unroll
            for (int it = 0; it < 4; it++) {
                int e = tid + it * 256;
                int row = e >> 3, ch = e & 7;
                uint32_t soff = (uint32_t)(row * 128 + ((ch ^ (row & 7)) << 4));
                size_t wsrc = (size_t)(m0 + row) * M_IND + k0 + ch * 8;
                size_t ssrc = (size_t)(n0 + row) * M_IND + k0 + ch * 8;
                CPA(buf + soff,         &g_Whi[wsrc]);
                CPA(buf + 16384 + soff, &g_Wlo[wsrc]);
                CPA(buf + 32768 + soff, &g_Shi[ssrc]);
                CPA(buf + 49152 + soff, &g_Slo[ssrc]);
            }
            CPC();
        }
        if (c == 0) continue;

        if (c < nchunks) { CPW1(); } else { CPW0(); }
        __syncthreads();

        int cc = c - 1;
        uint32_t buf = sbase + (uint32_t)(cc & 1) * STG_BYTES;
        uint32_t WHIa = buf, WLOa = buf + 16384, SHIa = buf + 32768, SLOa = buf + 49152;

#pragma unroll
        for (int kk = 0; kk < 4; kk++) {
            uint32_t A[4][4], Bf[2][4];
#pragma unroll
            for (int j2 = 0; j2 < 2; j2++) {
                int row = wn + j2 * 16 + lrow16;
                int ch = kk * 2 + lhalf;
                LDSM4(Bf[j2], SHIa + (uint32_t)(row * 128 + ((ch ^ (row & 7)) << 4)));
            }
#pragma unroll
            for (int i = 0; i < 4; i++) {
                int row = wm + i * 16 + lrow16;
                int ch = kk * 2 + lhalf;
                LDSM4(A[i], WHIa + (uint32_t)(row * 128 + ((ch ^ (row & 7)) << 4)));
            }
#pragma unroll
            for (int i = 0; i < 4; i++)
#pragma unroll
                for (int j = 0; j < 4; j++)
                    MMA16816(acc[i][j], A[i], Bf[j >> 1][j & 1], Bf[j >> 1][(j & 1) + 2]);
#pragma unroll
            for (int j2 = 0; j2 < 2; j2++) {
                int row = wn + j2 * 16 + lrow16;
                int ch = kk * 2 + lhalf;
                LDSM4(Bf[j2], SLOa + (uint32_t)(row * 128 + ((ch ^ (row & 7)) << 4)));
            }
#pragma unroll
            for (int i = 0; i < 4; i++)
#pragma unroll
                for (int j = 0; j < 4; j++)
                    MMA16816(acc[i][j], A[i], Bf[j >> 1][j & 1], Bf[j >> 1][(j & 1) + 2]);
#pragma unroll
            for (int i = 0; i < 4; i++) {
                int row = wm + i * 16 + lrow16;
                int ch = kk * 2 + lhalf;
                LDSM4(A[i], WLOa + (uint32_t)(row * 128 + ((ch ^ (row & 7)) << 4)));
            }
#pragma unroll
            for (int j2 = 0; j2 < 2; j2++) {
                int row = wn + j2 * 16 + lrow16;
                int ch = kk * 2 + lhalf;
                LDSM4(Bf[j2], SHIa + (uint32_t)(row * 128 + ((ch ^ (row & 7)) << 4)));
            }
#pragma unroll
            for (int i = 0; i < 4; i++)
#pragma unroll
                for (int j = 0; j < 4; j++)
                    MMA16816(acc[i][j], A[i], Bf[j >> 1][j & 1], Bf[j >> 1][(j & 1) + 2]);
        }
        __syncthreads();
    }

    float a1r[8], a2r[8];
#pragma unroll
    for (int i = 0; i < 4; i++)
#pragma unroll
        for (int rh = 0; rh < 2; rh++) {
            int row = wm + i * 16 + (lane >> 2) + rh * 8;
            a1r[i * 2 + rh] = a1s[row];
            a2r[i * 2 + rh] = a2s[row];
        }

    float pq[8], pm[8], pv[8];
#pragma unroll
    for (int j = 0; j < 4; j++)
#pragma unroll
        for (int cbit = 0; cbit < 2; cbit++) {
            float q = 0.f, m = 0.f, v = 0.f;
#pragma unroll
            for (int i = 0; i < 4; i++)
#pragma unroll
                for (int rh = 0; rh < 2; rh++) {
                    float x = acc[i][j][rh * 2 + cbit];
                    q += x * x;
                    m += x * a1r[i * 2 + rh];
                    v += x * a2r[i * 2 + rh];
                }
            pq[j * 2 + cbit] = q; pm[j * 2 + cbit] = m; pv[j * 2 + cbit] = v;
        }
#pragma unroll
    for (int off = 4; off <= 16; off <<= 1)
#pragma unroll
        for (int s = 0; s < 8; s++) {
            pq[s] += __shfl_xor_sync(0xffffffff, pq[s], off);
            pm[s] += __shfl_xor_sync(0xffffffff, pm[s], off);
            pv[s] += __shfl_xor_sync(0xffffffff, pv[s], off);
        }
    if (lane < 4) {
#pragma unroll
        for (int j = 0; j < 4; j++)
#pragma unroll
            for (int cbit = 0; cbit < 2; cbit++) {
                int col = j * 8 + lane * 2 + cbit;
                Rq[wid][col] = pq[j * 2 + cbit];
                Rm[wid][col] = pm[j * 2 + cbit];
                Rv[wid][col] = pv[j * 2 + cbit];
            }
    }
    __syncthreads();
    if (tid < 128) {
        int n = tid;
        int w = n >> 5, cl = n & 31;
        g_q[mb * SW + n0 + n]  = Rq[w][cl] + Rq[w + 4][cl];
        g_mm[mb * SW + n0 + n] = Rm[w][cl] + Rm[w + 4][cl];
        g_vv[mb * SW + n0 + n] = Rv[w][cl] + Rv[w + 4][cl];
    }
}

// ---------------------------------------------------------------------------
__global__ void reduce_out(float* __restrict__ out, const float* __restrict__ sv) {
    int n = blockIdx.x * 256 + threadIdx.x;
    if (n >= N_TE) return;
    float q = 0.f, mm = 0.f, vv = 0.f;
#pragma unroll
    for (int mb = 0; mb < 8; mb++) {
        q  += g_q[mb * SW + n];
        mm += g_mm[mb * SW + n];
        vv += g_vv[mb * SW + n];
    }
    float svv = fabsf(sv[0]);
    out[n] = mm;
    out[N_TE + n] = svv - q + vv * vv;
}

// ---------------------------------------------------------------------------
extern "C" void kernel_launch(void* const* d_in, const int* in_sizes, int n_in,
                              void* d_out, int out_size) {
    const float* Xte = (const float*)d_in[0];
    const float* xm  = (const float*)d_in[1];
    const float* qu  = (const float*)d_in[2];
    const float* ch  = (const float*)d_in[3];
    const float* ls  = (const float*)d_in[4];
    const float* sv  = (const float*)d_in[5];
    float* out = (float*)d_out;

    static bool attr_done = false;
    if (!attr_done) {
        cudaFuncSetAttribute(gemm_tc, cudaFuncAttributeMaxDynamicSharedMemorySize,
                             2 * STG_BYTES);
        cudaFuncSetAttribute(fact_kernel, cudaFuncAttributeMaxDynamicSharedMemorySize,
                             FACT_SMEM);
        attr_done = true;
    }

    fact_kernel<<<NBLK, 256, FACT_SMEM>>>(xm, qu, ch, ls, sv, Xte);
    gemm_tc<<<dim3(SW / 128, 8), 256, 2 * STG_BYTES>>>();
    reduce_out<<<(N_TE + 255) / 256, 256>>>(out, sv);
}

// round 13
// speedup vs baseline: 1.0687x; 1.0687x over previous
#include <cuda_runtime.h>
#include <cuda_bf16.h>
#include <math.h>
#include <stdint.h>

// Problem constants (fixed by setup_inputs)
#define N_TE   20000
#define M_IND  1024
#define D_DIM  16
#define BS     64
#define NB     16
#define SW     20096          // 314*64 padded width
#define JITTER 1e-3f
#define EPSV   1e-9f
#define NBLK   120            // persistent grid
#define NC     40             // group C (factorization) CTAs

typedef float Row[BS + 1];
#define FACT_SMEM (3 * BS * (BS + 1) * 4)
#define TSTRIDE 4160

// ---- PTX helpers ----------------------------------------------------------
__device__ __forceinline__ uint32_t smem_to_u32(const void* p) {
    uint32_t a;
    asm("{ .reg .u64 t; cvta.to.shared.u64 t, %1; cvt.u32.u64 %0, t; }" : "=r"(a) : "l"(p));
    return a;
}
#define CPA(dst, src) \
    asm volatile("cp.async.cg.shared.global [%0], [%1], 16;" :: "r"(dst), "l"(src))
#define CPC() asm volatile("cp.async.commit_group;" ::: "memory")
#define CPW0() asm volatile("cp.async.wait_group 0;" ::: "memory")
#define CPW1() asm volatile("cp.async.wait_group 1;" ::: "memory")
#define LDSM4(R, addr) \
    asm volatile("ldmatrix.sync.aligned.m8n8.x4.shared.b16 {%0,%1,%2,%3}, [%4];" \
        : "=r"((R)[0]), "=r"((R)[1]), "=r"((R)[2]), "=r"((R)[3]) : "r"(addr))
#define MMA16816(acc, a, b0_, b1_) \
    asm volatile("mma.sync.aligned.m16n8k16.row.col.f32.bf16.bf16.f32 " \
        "{%0,%1,%2,%3}, {%4,%5,%6,%7}, {%8,%9}, {%0,%1,%2,%3};" \
        : "+f"((acc)[0]), "+f"((acc)[1]), "+f"((acc)[2]), "+f"((acc)[3]) \
        : "r"((a)[0]), "r"((a)[1]), "r"((a)[2]), "r"((a)[3]), "r"(b0_), "r"(b1_))

// ---- fast 2^y for y <= 0 --------------------------------------------------
__device__ __forceinline__ float fexp2n(float y) {
    y = fmaxf(y, -125.0f);
    float r = y + 12582912.0f;
    int n = __float_as_int(r) - 0x4B400000;
    float f = y - (r - 12582912.0f);
    float p = 1.540353e-4f;
    p = fmaf(p, f, 1.3333558e-3f);
    p = fmaf(p, f, 9.6181296e-3f);
    p = fmaf(p, f, 5.5504109e-2f);
    p = fmaf(p, f, 2.4022651e-1f);
    p = fmaf(p, f, 6.9314718e-1f);
    p = fmaf(p, f, 1.0f);
    return __int_as_float(__float_as_int(p) + (n << 23));
}
#define NEG_HALF_LOG2E (-0.72134752f)

// ---- scratch --------------------------------------------------------------
__device__ float g_L[M_IND * M_IND];
__device__ float g_W[M_IND * M_IND];
__device__ float g_Zd[NB * BS * BS];
__device__ float g_tmp[512 * 512];
__device__ float g_xs[M_IND * D_DIM];
__device__ float g_nm[M_IND];
__device__ float g_a1[M_IND];
__device__ float g_a2[M_IND];
__device__ float g_q[8 * SW];
__device__ float g_mm[8 * SW];
__device__ float g_vv[8 * SW];
__device__ __nv_bfloat16 g_Whi[M_IND * M_IND];
__device__ __nv_bfloat16 g_Wlo[M_IND * M_IND];
__device__ __nv_bfloat16 g_Shi[(size_t)SW * M_IND];
__device__ __nv_bfloat16 g_Slo[(size_t)SW * M_IND];
__device__ unsigned g_cnt = 0;
__device__ volatile unsigned g_epoch = 0;
__device__ unsigned g_ccnt = 0;
__device__ volatile unsigned g_cepoch = 0;
__device__ volatile unsigned g_pflag[NB];

// ---------------------------------------------------------------------------
__device__ __forceinline__ void bar_gen(unsigned* cnt, volatile unsigned* ep,
                                        unsigned n, unsigned& sense) {
    __syncthreads();
    if (threadIdx.x == 0) {
        unsigned target = sense + 1;
        __threadfence();
        if (atomicAdd(cnt, 1u) == n - 1) {
            atomicExch(cnt, 0u);
            __threadfence();
            *ep = target;
        } else {
            while (*ep < target) { }
            __threadfence();
        }
    }
    __syncthreads();
    sense += 1;
}

// ---- swizzled flat tiles + microkernel (R12) ------------------------------
__device__ __forceinline__ float4 ldT4(const float* S, int r, int cb) {
    return *(const float4*)&S[r * 64 + (((cb) ^ (r >> 2)) & 15) * 4];
}
__device__ __forceinline__ void stT1(float* S, int r, int c, float v) {
    S[r * 64 + ((((c) >> 2) ^ (r >> 2)) & 15) * 4 + ((c) & 3)] = v;
}
__device__ __forceinline__ void load_direct(float* buf, const float* src, int stride, int tid) {
    for (int e = tid; e < 1024; e += 256) {
        int r = e >> 4, cb = e & 15;
        *(float4*)&buf[r * 64 + ((cb ^ (r >> 2)) & 15) * 4] =
            *(const float4*)&src[(size_t)r * stride + cb * 4];
    }
}
__device__ __forceinline__ void load_trans(float* buf, const float* src, int stride, int tid) {
    for (int e = tid; e < 1024; e += 256) {
        int i = e >> 4, c4 = (e & 15) * 4;
        float4 v = *(const float4*)&src[(size_t)i * stride + c4];
        stT1(buf, c4 + 0, i, v.x);
        stT1(buf, c4 + 1, i, v.y);
        stT1(buf, c4 + 2, i, v.z);
        stT1(buf, c4 + 3, i, v.w);
    }
}
template <bool SUB>
__device__ __forceinline__ void mm64(const float* A, const float* B,
                                     float (&acc)[4][4], int ty4, int tx4) {
#pragma unroll
    for (int cb = 0; cb < 16; cb++) {
        float4 a[4], b[4];
#pragma unroll
        for (int ii = 0; ii < 4; ii++) a[ii] = ldT4(A, ty4 + ii, cb);
#pragma unroll
        for (int jj = 0; jj < 4; jj++) b[jj] = ldT4(B, tx4 + jj, cb);
#pragma unroll
        for (int ii = 0; ii < 4; ii++)
#pragma unroll
            for (int jj = 0; jj < 4; jj++) {
                if (SUB) {
                    acc[ii][jj] = fmaf(-a[ii].x, b[jj].x, acc[ii][jj]);
                    acc[ii][jj] = fmaf(-a[ii].y, b[jj].y, acc[ii][jj]);
                    acc[ii][jj] = fmaf(-a[ii].z, b[jj].z, acc[ii][jj]);
                    acc[ii][jj] = fmaf(-a[ii].w, b[jj].w, acc[ii][jj]);
                } else {
                    acc[ii][jj] = fmaf(a[ii].x, b[jj].x, acc[ii][jj]);
                    acc[ii][jj] = fmaf(a[ii].y, b[jj].y, acc[ii][jj]);
                    acc[ii][jj] = fmaf(a[ii].z, b[jj].z, acc[ii][jj]);
                    acc[ii][jj] = fmaf(a[ii].w, b[jj].w, acc[ii][jj]);
                }
            }
    }
}

// ---------------------------------------------------------------------------
// 64x64 Cholesky factor + inverse -> g_Zd + W diag
// ---------------------------------------------------------------------------
__device__ void factor_inverse(Row* Lb, Row* Zb, int kout) {
    __shared__ float Mtmp[7 * 64];
    int tid = threadIdx.x, tx = tid % 16, ty = tid / 16;

    for (int e = tid; e < BS * BS; e += 256)
        Zb[e / BS][e % BS] = 0.f;
    __syncthreads();

    for (int j = 0; j < BS - 1; j++) {
        float inv = 1.f / Lb[j][j];
        for (int r = j + 1 + ty; r < BS; r += 16) {
            float lrj = Lb[r][j] * inv;
            for (int c = j + 1 + tx; c <= r; c += 16)
                Lb[r][c] -= lrj * Lb[c][j];
        }
        __syncthreads();
    }
    float vals[16];
    int q = 0;
    for (int e = tid; e < BS * BS; e += 256, q++) {
        int r = e / BS, c = e % BS;
        float v = Lb[r][c];
        if (c < r)       v *= rsqrtf(Lb[c][c]);
        else if (c == r) v = sqrtf(v);
        else             v = 0.f;
        vals[q] = v;
    }
    __syncthreads();
    q = 0;
    for (int e = tid; e < BS * BS; e += 256, q++)
        Lb[e / BS][e % BS] = vals[q];
    __syncthreads();

    if (tid < 64) {
        int g = tid >> 3, c = tid & 7, b0 = g * 8;
        Zb[b0 + c][b0 + c] = 1.f / Lb[b0 + c][b0 + c];
        for (int r = c + 1; r < 8; r++) {
            float s = 0.f;
            for (int k = c; k < r; k++)
                s += Lb[b0 + r][b0 + k] * Zb[b0 + k][b0 + c];
            Zb[b0 + r][b0 + c] = -s / Lb[b0 + r][b0 + r];
        }
    }
    __syncthreads();

    for (int bi = 1; bi < 8; bi++) {
        int tot = bi * 64;
        for (int e = tid; e < tot; e += 256) {
            int bj = e >> 6, rc = e & 63, r = rc >> 3, c = rc & 7;
            float s = 0.f;
            for (int k = bj * 8; k < bi * 8; k++)
                s += Lb[bi * 8 + r][k] * Zb[k][bj * 8 + c];
            Mtmp[e] = s;
        }
        __syncthreads();
        for (int e = tid; e < tot; e += 256) {
            int bj = e >> 6, rc = e & 63, r = rc >> 3, c = rc & 7;
            float s = 0.f;
#pragma unroll
            for (int t = 0; t < 8; t++)
                s += Zb[bi * 8 + r][bi * 8 + t] * Mtmp[bj * 64 + t * 8 + c];
            Zb[bi * 8 + r][bj * 8 + c] = -s;
        }
        __syncthreads();
    }

    for (int e = tid; e < BS * BS; e += 256) {
        int r = e / BS, c = e % BS;
        float v = Zb[r][c];
        g_Zd[kout * BS * BS + e] = v;
        g_W[(size_t)(kout * BS + r) * M_IND + kout * BS + c] = v;
    }
    __syncthreads();
}

// ---------------------------------------------------------------------------
// Kernel 1: prep + K_mm + Cholesky (C group) ; Shi/Slo build (S group)
// ---------------------------------------------------------------------------
__global__ void __launch_bounds__(256, 1) fact_kernel(const float* __restrict__ xm,
                                                      const float* __restrict__ ls,
                                                      const float* __restrict__ sv,
                                                      const float* __restrict__ Xte) {
    extern __shared__ __align__(16) float sm[];
    float* SA = sm;
    float* SB = sm + TSTRIDE;
    float* SC = sm + 2 * TSTRIDE;
    Row* SAr = (Row*)SA;
    Row* SBr = (Row*)SB;
    __shared__ unsigned sh_a, sh_c;
    int tid = threadIdx.x, bid = blockIdx.x;
    if (tid == 0) { sh_a = g_epoch; sh_c = g_cepoch; }
    __syncthreads();
    unsigned s_all = sh_a, s_c = sh_c;
    const unsigned basec = s_c;

    int gthread = bid * 256 + tid;
    int tx = tid % 16, ty = tid / 16;
    int tx4 = tx * 4, ty4 = ty * 4;
    float svv = fabsf(sv[0]);

    // phase 1 (all): pre-scaled xm rows + norms
    for (int m = gthread; m < M_IND; m += NBLK * 256) {
        float nrm = 0.f;
#pragma unroll
        for (int d = 0; d < D_DIM; d++) {
            float il = 1.f / (fabsf(ls[d]) + EPSV);
            float v = xm[m * D_DIM + d] * il;
            g_xs[m * D_DIM + d] = v;
            nrm += v * v;
        }
        g_nm[m] = nrm;
    }
    bar_gen(&g_cnt, &g_epoch, NBLK, s_all);

    if (bid >= NC) {
        // ================= group S: build Shi/Slo, then exit =============
        float* Xs = SA;
        float* Ms = SB;
        int ntile = (SW / 64) * (M_IND / 32);
        for (int x = bid - NC; x < ntile; x += NBLK - NC) {
            int n0 = (x % (SW / 64)) * 64, m0 = (x / (SW / 64)) * 32;
            for (int e = tid; e < 64 * D_DIM; e += 256) {
                int i = e / D_DIM, d = e % D_DIM;
                int n = n0 + i;
                float il = 1.f / (fabsf(ls[d]) + EPSV);
                Xs[i * 17 + d] = (n < N_TE) ? Xte[n * D_DIM + d] * il : 0.f;
            }
            for (int e = tid; e < 32 * D_DIM; e += 256) {
                int i = e / D_DIM, d = e % D_DIM;
                Ms[i * 17 + d] = g_xs[(m0 + i) * D_DIM + d];
            }
            __syncthreads();

            int sx = tid % 64, sy = tid / 64;
            int n = n0 + sx;
            __align__(16) __nv_bfloat16 h8[8];
            __align__(16) __nv_bfloat16 l8[8];
#pragma unroll
            for (int mi = 0; mi < 8; mi++) {
                int ml = sy * 8 + mi;
                float outv = 0.f;
                if (n < N_TE) {
                    float d2 = 0.f;
#pragma unroll
                    for (int d = 0; d < D_DIM; d++) {
                        float diff = Xs[sx * 17 + d] - Ms[ml * 17 + d];
                        d2 += diff * diff;
                    }
                    outv = svv * fexp2n(d2 * NEG_HALF_LOG2E);
                }
                __nv_bfloat16 h = __float2bfloat16(outv);
                h8[mi] = h;
                l8[mi] = __float2bfloat16(outv - __bfloat162float(h));
            }
            size_t off = (size_t)n * M_IND + m0 + sy * 8;
            *(uint4*)&g_Shi[off] = *(uint4*)h8;
            *(uint4*)&g_Slo[off] = *(uint4*)l8;
            __syncthreads();
        }
        return;
    }

    // ================= group C: K_mm + Cholesky =================
    for (int x = bid; x < NB * (NB + 1) / 2; x += NC) {
        int br = 0;
        while ((br + 1) * (br + 2) / 2 <= x) br++;
        int bc = x - br * (br + 1) / 2;
        for (int e = tid; e < 64 * D_DIM; e += 256) {
            int i = e >> 4, d = e & 15;
            SAr[i][d] = g_xs[(br * 64 + i) * D_DIM + d];
            SBr[i][d] = g_xs[(bc * 64 + i) * D_DIM + d];
        }
        if (tid < 64) {
            SAr[tid][16] = g_nm[br * 64 + tid];
            SBr[tid][16] = g_nm[bc * 64 + tid];
        }
        __syncthreads();
        float dot[4][4] = {};
#pragma unroll
        for (int d = 0; d < D_DIM; d++) {
            float av[4], bv[4];
#pragma unroll
            for (int ii = 0; ii < 4; ii++) av[ii] = SAr[ty4 + ii][d];
#pragma unroll
            for (int jj = 0; jj < 4; jj++) bv[jj] = SBr[tx4 + jj][d];
#pragma unroll
            for (int ii = 0; ii < 4; ii++)
#pragma unroll
                for (int jj = 0; jj < 4; jj++) dot[ii][jj] += av[ii] * bv[jj];
        }
#pragma unroll
        for (int ii = 0; ii < 4; ii++) {
            int gr = br * 64 + ty4 + ii;
            float nr = SAr[ty4 + ii][16];
#pragma unroll
            for (int jj = 0; jj < 4; jj++) {
                int gc = bc * 64 + tx4 + jj;
                float d2 = fmaxf(nr + SBr[tx4 + jj][16] - 2.f * dot[ii][jj], 0.f);
                float v = svv * fexp2n(d2 * NEG_HALF_LOG2E);
                if (gr == gc) v += JITTER;
                g_L[(size_t)gr * M_IND + gc] = v;
            }
        }
        __syncthreads();
    }
    if (bid == 0) {
        for (int e = tid; e < BS * BS; e += 256)
            SAr[e / BS][e % BS] = g_L[(size_t)(e / BS) * M_IND + (e % BS)];
        __syncthreads();
        factor_inverse(SAr, SBr, 0);
    }
    bar_gen(&g_ccnt, &g_cepoch, NC, s_c);

    for (int k = 0; k < NB - 1; k++) {
        int o = k * BS, t = NB - 1 - k;
        unsigned target = basec + (unsigned)(k + 1);

        if (bid == 0) {
            int bi = k + 1;
            load_direct(SA, &g_L[(size_t)(bi * BS) * M_IND + o], M_IND, tid);
            load_direct(SB, &g_Zd[k * BS * BS], BS, tid);
            __syncthreads();
            float acc[4][4] = {};
            mm64<false>(SA, SB, acc, ty4, tx4);
#pragma unroll
            for (int ii = 0; ii < 4; ii++) {
                *(float4*)&g_L[(size_t)(bi * BS + ty4 + ii) * M_IND + o + tx4] =
                    make_float4(acc[ii][0], acc[ii][1], acc[ii][2], acc[ii][3]);
                *(float4*)&SC[(ty4 + ii) * 64 + ((tx ^ ((ty4 + ii) >> 2)) & 15) * 4] =
                    make_float4(acc[ii][0], acc[ii][1], acc[ii][2], acc[ii][3]);
            }
            __threadfence();
            __syncthreads();
            if (tid == 0) g_pflag[bi] = target;
            float u[4][4];
#pragma unroll
            for (int ii = 0; ii < 4; ii++) {
                float4 v = *(const float4*)&g_L[(size_t)(bi * BS + ty4 + ii) * M_IND + bi * BS + tx4];
                u[ii][0] = v.x; u[ii][1] = v.y; u[ii][2] = v.z; u[ii][3] = v.w;
            }
            mm64<true>(SC, SC, u, ty4, tx4);
            __syncthreads();
#pragma unroll
            for (int ii = 0; ii < 4; ii++)
#pragma unroll
                for (int jj = 0; jj < 4; jj++)
                    SAr[ty4 + ii][tx4 + jj] = u[ii][jj];
            factor_inverse(SAr, SBr, bi);
        } else {
            for (int p = bid - 1; p < t - 1; p += NC - 1) {
                int bi = k + 2 + p;
                load_direct(SA, &g_L[(size_t)(bi * BS) * M_IND + o], M_IND, tid);
                load_direct(SB, &g_Zd[k * BS * BS], BS, tid);
                __syncthreads();
                float acc[4][4] = {};
                mm64<false>(SA, SB, acc, ty4, tx4);
#pragma unroll
                for (int ii = 0; ii < 4; ii++)
                    *(float4*)&g_L[(size_t)(bi * BS + ty4 + ii) * M_IND + o + tx4] =
                        make_float4(acc[ii][0], acc[ii][1], acc[ii][2], acc[ii][3]);
                __threadfence();
                __syncthreads();
                if (tid == 0) g_pflag[bi] = target;
            }
            int ntile = t * (t + 1) / 2;
            for (int x = bid; x < ntile; x += NC - 1) {
                int r = 0;
                while ((r + 1) * (r + 2) / 2 <= x) r++;
                int c = x - r * (r + 1) / 2;
                int bi = k + 1 + r, bj = k + 1 + c;
                if (tid == 0) {
                    while (g_pflag[bi] < target) { }
                    while (g_pflag[bj] < target) { }
                    __threadfence();
                }
                __syncthreads();
                load_direct(SA, &g_L[(size_t)(bi * BS) * M_IND + o], M_IND, tid);
                load_direct(SB, &g_L[(size_t)(bj * BS) * M_IND + o], M_IND, tid);
                __syncthreads();
                float u[4][4];
#pragma unroll
                for (int ii = 0; ii < 4; ii++) {
                    float4 v = *(const float4*)&g_L[(size_t)(bi * BS + ty4 + ii) * M_IND + bj * BS + tx4];
                    u[ii][0] = v.x; u[ii][1] = v.y; u[ii][2] = v.z; u[ii][3] = v.w;
                }
                mm64<true>(SA, SB, u, ty4, tx4);
#pragma unroll
                for (int ii = 0; ii < 4; ii++)
                    *(float4*)&g_L[(size_t)(bi * BS + ty4 + ii) * M_IND + bj * BS + tx4] =
                        make_float4(u[ii][0], u[ii][1], u[ii][2], u[ii][3]);
                __syncthreads();
            }
        }
        bar_gen(&g_ccnt, &g_cepoch, NC, s_c);
    }
}

// ---------------------------------------------------------------------------
// Doubling kernels (separately launched, grid-parallel, no soft barriers)
// ---------------------------------------------------------------------------
__global__ void __launch_bounds__(256, 1) dbl0_kernel() {
    extern __shared__ __align__(16) float sm[];
    float* SA = sm;
    float* SB = sm + TSTRIDE;
    float* SC = sm + 2 * TSTRIDE;
    int tid = threadIdx.x;
    int tx4 = (tid % 16) * 4, ty4 = (tid / 16) * 4;
    int base = blockIdx.x * 128;

    load_direct(SA, &g_L[(size_t)(base + 64) * M_IND + base], M_IND, tid);   // L21
    load_trans(SB, &g_W[(size_t)base * M_IND + base], M_IND, tid);           // W11^T
    __syncthreads();
    float acc[4][4] = {};
    mm64<false>(SA, SB, acc, ty4, tx4);
    __syncthreads();
#pragma unroll
    for (int ii = 0; ii < 4; ii++)
#pragma unroll
        for (int jj = 0; jj < 4; jj++)
            stT1(SC, tx4 + jj, ty4 + ii, acc[ii][jj]);
    __syncthreads();
    load_direct(SA, &g_W[(size_t)(base + 64) * M_IND + base + 64], M_IND, tid);  // W22
    __syncthreads();
    float ac2[4][4] = {};
    mm64<false>(SA, SC, ac2, ty4, tx4);
#pragma unroll
    for (int ii = 0; ii < 4; ii++)
        *(float4*)&g_W[(size_t)(base + 64 + ty4 + ii) * M_IND + base + tx4] =
            make_float4(-ac2[ii][0], -ac2[ii][1], -ac2[ii][2], -ac2[ii][3]);
}

__global__ void __launch_bounds__(256, 1) dblA_kernel(int l) {
    extern __shared__ __align__(16) float sm[];
    float* SA = sm;
    float* SB = sm + TSTRIDE;
    int tid = threadIdx.x;
    int tx4 = (tid % 16) * 4, ty4 = (tid / 16) * 4;
    int s = 64 << l, tt = 1 << l;
    int x = blockIdx.x;
    int p = x / (tt * tt), rem = x % (tt * tt), tr = rem / tt, tc = rem % tt;
    int base = p * 2 * s;
    float acc[4][4] = {};
    for (int k0 = tc * BS; k0 < s; k0 += BS) {
        load_direct(SA, &g_L[(size_t)(base + s + tr * BS) * M_IND + base + k0], M_IND, tid);
        load_trans(SB, &g_W[(size_t)(base + k0) * M_IND + base + tc * BS], M_IND, tid);
        __syncthreads();
        mm64<false>(SA, SB, acc, ty4, tx4);
        __syncthreads();
    }
#pragma unroll
    for (int ii = 0; ii < 4; ii++)
        *(float4*)&g_tmp[(size_t)p * s * s + (tr * BS + ty4 + ii) * s + tc * BS + tx4] =
            make_float4(acc[ii][0], acc[ii][1], acc[ii][2], acc[ii][3]);
}

__global__ void __launch_bounds__(256, 1) dblB_kernel(int l) {
    extern __shared__ __align__(16) float sm[];
    float* SA = sm;
    float* SB = sm + TSTRIDE;
    int tid = threadIdx.x;
    int tx4 = (tid % 16) * 4, ty4 = (tid / 16) * 4;
    int s = 64 << l, tt = 1 << l;
    int x = blockIdx.x;
    int p = x / (tt * tt), rem = x % (tt * tt), tr = rem / tt, tc = rem % tt;
    int base = p * 2 * s;
    float acc[4][4] = {};
    for (int k0 = 0; k0 <= tr * BS; k0 += BS) {
        load_direct(SA, &g_W[(size_t)(base + s + tr * BS) * M_IND + base + s + k0], M_IND, tid);
        load_trans(SB, &g_tmp[(size_t)p * s * s + (size_t)k0 * s + tc * BS], s, tid);
        __syncthreads();
        mm64<false>(SA, SB, acc, ty4, tx4);
        __syncthreads();
    }
#pragma unroll
    for (int ii = 0; ii < 4; ii++)
        *(float4*)&g_W[(size_t)(base + s + tr * BS + ty4 + ii) * M_IND + base + tc * BS + tx4] =
            make_float4(-acc[ii][0], -acc[ii][1], -acc[ii][2], -acc[ii][3]);
}

// ---------------------------------------------------------------------------
// Final: bf16 split of W (mask unwritten upper) + a1/a2 (grid-stride)
// ---------------------------------------------------------------------------
__global__ void final_kernel(const float* __restrict__ qu, const float* __restrict__ ch) {
    int gthread = blockIdx.x * 256 + threadIdx.x;
    int nth = gridDim.x * 256;
    for (int idx = gthread; idx < M_IND * M_IND; idx += nth) {
        int r = idx >> 10, c = idx & 1023;
        float w = ((c >> 6) <= (r >> 6)) ? g_W[idx] : 0.f;
        __nv_bfloat16 h = __float2bfloat16(w);
        g_Whi[idx] = h;
        g_Wlo[idx] = __float2bfloat16(w - __bfloat162float(h));
    }
    int wid = gthread / 32, lane = threadIdx.x % 32, nw = nth / 32;
    for (int r = wid; r < M_IND; r += nw) {
        float s1 = 0.f, s2 = 0.f;
        for (int c = lane; c <= r; c += 32) {
            float w = g_W[(size_t)r * M_IND + c];
            s1 += w * qu[c];
            s2 += w * ch[c];
        }
#pragma unroll
        for (int off = 16; off; off >>= 1) {
            s1 += __shfl_down_sync(0xffffffff, s1, off);
            s2 += __shfl_down_sync(0xffffffff, s2, off);
        }
        if (lane == 0) { g_a1[r] = s1; g_a2[r] = s2; }
    }
}

// ---------------------------------------------------------------------------
// Warp-MMA bf16 GEMM + fused epilogue (round-5/6 proven)
// ---------------------------------------------------------------------------
#define STG_BYTES 65536
__global__ void __launch_bounds__(256) gemm_tc() {
    extern __shared__ __align__(1024) char dsm[];
    __shared__ float Rq[8][32], Rm[8][32], Rv[8][32];
    __shared__ float a1s[128], a2s[128];

    const uint32_t sbase = smem_to_u32(dsm);
    int tid = threadIdx.x, wid = tid >> 5, lane = tid & 31;
    int n0 = blockIdx.x * 128;
    int mb = 7 - (int)blockIdx.y;
    int m0 = mb * 128;
    int nchunks = (m0 + 128) >> 6;

    if (tid < 128) { a1s[tid] = g_a1[m0 + tid]; a2s[tid] = g_a2[m0 + tid]; }

    int wm = (wid >> 2) * 64;
    int wn = (wid & 3) * 32;
    int lrow16 = lane & 15, lhalf = lane >> 4;

    float acc[4][4][4];
#pragma unroll
    for (int i = 0; i < 4; i++)
#pragma unroll
        for (int j = 0; j < 4; j++)
#pragma unroll
            for (int r = 0; r < 4; r++) acc[i][j][r] = 0.f;

    for (int c = 0; c < nchunks + 1; c++) {
        if (c < nchunks) {
            int k0 = c << 6;
            uint32_t buf = sbase + (uint32_t)(c & 1) * STG_BYTES;
#pragma unroll
            for (int it = 0; it < 4; it++) {
                int e = tid + it * 256;
                int row = e >> 3, ch = e & 7;
                uint32_t soff = (uint32_t)(row * 128 + ((ch ^ (row & 7)) << 4));
                size_t wsrc = (size_t)(m0 + row) * M_IND + k0 + ch * 8;
                size_t ssrc = (size_t)(n0 + row) * M_IND + k0 + ch * 8;
                CPA(buf + soff,         &g_Whi[wsrc]);
                CPA(buf + 16384 + soff, &g_Wlo[wsrc]);
                CPA(buf + 32768 + soff, &g_Shi[ssrc]);
                CPA(buf + 49152 + soff, &g_Slo[ssrc]);
            }
            CPC();
        }
        if (c == 0) continue;

        if (c < nchunks) { CPW1(); } else { CPW0(); }
        __syncthreads();

        int cc = c - 1;
        uint32_t buf = sbase + (uint32_t)(cc & 1) * STG_BYTES;
        uint32_t WHIa = buf, WLOa = buf + 16384, SHIa = buf + 32768, SLOa = buf + 49152;

#pragma unroll
        for (int kk = 0; kk < 4; kk++) {
            uint32_t A[4][4], Bf[2][4];
#pragma unroll
            for (int j2 = 0; j2 < 2; j2++) {
                int row = wn + j2 * 16 + lrow16;
                int ch = kk * 2 + lhalf;
                LDSM4(Bf[j2], SHIa + (uint32_t)(row * 128 + ((ch ^ (row & 7)) << 4)));
            }
#pragma unroll
            for (int i = 0; i < 4; i++) {
                int row = wm + i * 16 + lrow16;
                int ch = kk * 2 + lhalf;
                LDSM4(A[i], WHIa + (uint32_t)(row * 128 + ((ch ^ (row & 7)) << 4)));
            }
#pragma unroll
            for (int i = 0; i < 4; i++)
#pragma unroll
                for (int j = 0; j < 4; j++)
                    MMA16816(acc[i][j], A[i], Bf[j >> 1][j & 1], Bf[j >> 1][(j & 1) + 2]);
#pragma unroll
            for (int j2 = 0; j2 < 2; j2++) {
                int row = wn + j2 * 16 + lrow16;
                int ch = kk * 2 + lhalf;
                LDSM4(Bf[j2], SLOa + (uint32_t)(row * 128 + ((ch ^ (row & 7)) << 4)));
            }
#pragma unroll
            for (int i = 0; i < 4; i++)
#pragma unroll
                for (int j = 0; j < 4; j++)
                    MMA16816(acc[i][j], A[i], Bf[j >> 1][j & 1], Bf[j >> 1][(j & 1) + 2]);
#pragma unroll
            for (int i = 0; i < 4; i++) {
                int row = wm + i * 16 + lrow16;
                int ch = kk * 2 + lhalf;
                LDSM4(A[i], WLOa + (uint32_t)(row * 128 + ((ch ^ (row & 7)) << 4)));
            }
#pragma unroll
            for (int j2 = 0; j2 < 2; j2++) {
                int row = wn + j2 * 16 + lrow16;
                int ch = kk * 2 + lhalf;
                LDSM4(Bf[j2], SHIa + (uint32_t)(row * 128 + ((ch ^ (row & 7)) << 4)));
            }
#pragma unroll
            for (int i = 0; i < 4; i++)
#pragma unroll
                for (int j = 0; j < 4; j++)
                    MMA16816(acc[i][j], A[i], Bf[j >> 1][j & 1], Bf[j >> 1][(j & 1) + 2]);
        }
        __syncthreads();
    }

    float a1r[8], a2r[8];
#pragma unroll
    for (int i = 0; i < 4; i++)
#pragma unroll
        for (int rh = 0; rh < 2; rh++) {
            int row = wm + i * 16 + (lane >> 2) + rh * 8;
            a1r[i * 2 + rh] = a1s[row];
            a2r[i * 2 + rh] = a2s[row];
        }

    float pq[8], pm[8], pv[8];
#pragma unroll
    for (int j = 0; j < 4; j++)
#pragma unroll
        for (int cbit = 0; cbit < 2; cbit++) {
            float q = 0.f, m = 0.f, v = 0.f;
#pragma unroll
            for (int i = 0; i < 4; i++)
#pragma unroll
                for (int rh = 0; rh < 2; rh++) {
                    float x = acc[i][j][rh * 2 + cbit];
                    q += x * x;
                    m += x * a1r[i * 2 + rh];
                    v += x * a2r[i * 2 + rh];
                }
            pq[j * 2 + cbit] = q; pm[j * 2 + cbit] = m; pv[j * 2 + cbit] = v;
        }
#pragma unroll
    for (int off = 4; off <= 16; off <<= 1)
#pragma unroll
        for (int s = 0; s < 8; s++) {
            pq[s] += __shfl_xor_sync(0xffffffff, pq[s], off);
            pm[s] += __shfl_xor_sync(0xffffffff, pm[s], off);
            pv[s] += __shfl_xor_sync(0xffffffff, pv[s], off);
        }
    if (lane < 4) {
#pragma unroll
        for (int j = 0; j < 4; j++)
#pragma unroll
            for (int cbit = 0; cbit < 2; cbit++) {
                int col = j * 8 + lane * 2 + cbit;
                Rq[wid][col] = pq[j * 2 + cbit];
                Rm[wid][col] = pm[j * 2 + cbit];
                Rv[wid][col] = pv[j * 2 + cbit];
            }
    }
    __syncthreads();
    if (tid < 128) {
        int n = tid;
        int w = n >> 5, cl = n & 31;
        g_q[mb * SW + n0 + n]  = Rq[w][cl] + Rq[w + 4][cl];
        g_mm[mb * SW + n0 + n] = Rm[w][cl] + Rm[w + 4][cl];
        g_vv[mb * SW + n0 + n] = Rv[w][cl] + Rv[w + 4][cl];
    }
}

// ---------------------------------------------------------------------------
__global__ void reduce_out(float* __restrict__ out, const float* __restrict__ sv) {
    int n = blockIdx.x * 256 + threadIdx.x;
    if (n >= N_TE) return;
    float q = 0.f, mm = 0.f, vv = 0.f;
#pragma unroll
    for (int mb = 0; mb < 8; mb++) {
        q  += g_q[mb * SW + n];
        mm += g_mm[mb * SW + n];
        vv += g_vv[mb * SW + n];
    }
    float svv = fabsf(sv[0]);
    out[n] = mm;
    out[N_TE + n] = svv - q + vv * vv;
}

// ---------------------------------------------------------------------------
extern "C" void kernel_launch(void* const* d_in, const int* in_sizes, int n_in,
                              void* d_out, int out_size) {
    const float* Xte = (const float*)d_in[0];
    const float* xm  = (const float*)d_in[1];
    const float* qu  = (const float*)d_in[2];
    const float* ch  = (const float*)d_in[3];
    const float* ls  = (const float*)d_in[4];
    const float* sv  = (const float*)d_in[5];
    float* out = (float*)d_out;

    static bool attr_done = false;
    if (!attr_done) {
        cudaFuncSetAttribute(gemm_tc, cudaFuncAttributeMaxDynamicSharedMemorySize,
                             2 * STG_BYTES);
        cudaFuncSetAttribute(fact_kernel, cudaFuncAttributeMaxDynamicSharedMemorySize,
                             FACT_SMEM);
        cudaFuncSetAttribute(dbl0_kernel, cudaFuncAttributeMaxDynamicSharedMemorySize,
                             FACT_SMEM);
        cudaFuncSetAttribute(dblA_kernel, cudaFuncAttributeMaxDynamicSharedMemorySize,
                             FACT_SMEM);
        cudaFuncSetAttribute(dblB_kernel, cudaFuncAttributeMaxDynamicSharedMemorySize,
                             FACT_SMEM);
        attr_done = true;
    }

    fact_kernel<<<NBLK, 256, FACT_SMEM>>>(xm, ls, sv, Xte);
    dbl0_kernel<<<8, 256, FACT_SMEM>>>();
    for (int l = 1; l < 4; l++) {
        int tiles = 8 << l;
        dblA_kernel<<<tiles, 256, FACT_SMEM>>>(l);
        dblB_kernel<<<tiles, 256, FACT_SMEM>>>(l);
    }
    final_kernel<<<240, 256>>>(qu, ch);
    gemm_tc<<<dim3(SW / 128, 8), 256, 2 * STG_BYTES>>>();
    reduce_out<<<(N_TE + 255) / 256, 256>>>(out, sv);
}

// round 14
// speedup vs baseline: 1.1228x; 1.0506x over previous
#include <cuda_runtime.h>
#include <cuda_bf16.h>
#include <math.h>
#include <stdint.h>

// Problem constants (fixed by setup_inputs)
#define N_TE   20000
#define M_IND  1024
#define D_DIM  16
#define BS     64
#define NB     16
#define SW     20096          // 314*64 padded width
#define JITTER 1e-3f
#define EPSV   1e-9f
#define NBLK   120            // persistent grid
#define NC     61             // group C (factorization) CTAs

typedef float Row[BS + 1];
#define FACT_SMEM (3 * BS * (BS + 1) * 4)
#define TSTRIDE 4160

// ---- PTX helpers ----------------------------------------------------------
__device__ __forceinline__ uint32_t smem_to_u32(const void* p) {
    uint32_t a;
    asm("{ .reg .u64 t; cvta.to.shared.u64 t, %1; cvt.u32.u64 %0, t; }" : "=r"(a) : "l"(p));
    return a;
}
#define CPA(dst, src) \
    asm volatile("cp.async.cg.shared.global [%0], [%1], 16;" :: "r"(dst), "l"(src))
#define CPC() asm volatile("cp.async.commit_group;" ::: "memory")
#define CPW0() asm volatile("cp.async.wait_group 0;" ::: "memory")
#define CPW1() asm volatile("cp.async.wait_group 1;" ::: "memory")
#define LDSM4(R, addr) \
    asm volatile("ldmatrix.sync.aligned.m8n8.x4.shared.b16 {%0,%1,%2,%3}, [%4];" \
        : "=r"((R)[0]), "=r"((R)[1]), "=r"((R)[2]), "=r"((R)[3]) : "r"(addr))
#define MMA16816(acc, a, b0_, b1_) \
    asm volatile("mma.sync.aligned.m16n8k16.row.col.f32.bf16.bf16.f32 " \
        "{%0,%1,%2,%3}, {%4,%5,%6,%7}, {%8,%9}, {%0,%1,%2,%3};" \
        : "+f"((acc)[0]), "+f"((acc)[1]), "+f"((acc)[2]), "+f"((acc)[3]) \
        : "r"((a)[0]), "r"((a)[1]), "r"((a)[2]), "r"((a)[3]), "r"(b0_), "r"(b1_))

// ---- fast 2^y for y <= 0 --------------------------------------------------
__device__ __forceinline__ float fexp2n(float y) {
    y = fmaxf(y, -125.0f);
    float r = y + 12582912.0f;
    int n = __float_as_int(r) - 0x4B400000;
    float f = y - (r - 12582912.0f);
    float p = 1.540353e-4f;
    p = fmaf(p, f, 1.3333558e-3f);
    p = fmaf(p, f, 9.6181296e-3f);
    p = fmaf(p, f, 5.5504109e-2f);
    p = fmaf(p, f, 2.4022651e-1f);
    p = fmaf(p, f, 6.9314718e-1f);
    p = fmaf(p, f, 1.0f);
    return __int_as_float(__float_as_int(p) + (n << 23));
}
#define NEG_HALF_LOG2E (-0.72134752f)

// ---- scratch --------------------------------------------------------------
__device__ float g_L[M_IND * M_IND];
__device__ float g_W[M_IND * M_IND];
__device__ float g_Zd[NB * BS * BS];
__device__ float g_tmp[512 * 512];
__device__ float g_xs[M_IND * D_DIM];
__device__ float g_nm[M_IND];
__device__ float g_a1[M_IND];
__device__ float g_a2[M_IND];
__device__ float g_q[8 * SW];
__device__ float g_mm[8 * SW];
__device__ float g_vv[8 * SW];
__device__ __nv_bfloat16 g_Whi[M_IND * M_IND];
__device__ __nv_bfloat16 g_Wlo[M_IND * M_IND];
__device__ __nv_bfloat16 g_Shi[(size_t)SW * M_IND];
__device__ __nv_bfloat16 g_Slo[(size_t)SW * M_IND];
__device__ unsigned g_cnt = 0;
__device__ volatile unsigned g_epoch = 0;
__device__ unsigned g_ccnt = 0;
__device__ volatile unsigned g_cepoch = 0;
__device__ volatile unsigned g_pflag[NB];

// ---------------------------------------------------------------------------
__device__ __forceinline__ void bar_gen(unsigned* cnt, volatile unsigned* ep,
                                        unsigned n, unsigned& sense) {
    __syncthreads();
    if (threadIdx.x == 0) {
        unsigned target = sense + 1;
        __threadfence();
        if (atomicAdd(cnt, 1u) == n - 1) {
            atomicExch(cnt, 0u);
            __threadfence();
            *ep = target;
        } else {
            while (*ep < target) { }
            __threadfence();
        }
    }
    __syncthreads();
    sense += 1;
}

// ---- swizzled flat tiles + microkernel ------------------------------------
__device__ __forceinline__ float4 ldT4(const float* S, int r, int cb) {
    return *(const float4*)&S[r * 64 + (((cb) ^ (r >> 2)) & 15) * 4];
}
__device__ __forceinline__ void stT1(float* S, int r, int c, float v) {
    S[r * 64 + ((((c) >> 2) ^ (r >> 2)) & 15) * 4 + ((c) & 3)] = v;
}
__device__ __forceinline__ void load_direct(float* buf, const float* src, int stride, int tid) {
    for (int e = tid; e < 1024; e += 256) {
        int r = e >> 4, cb = e & 15;
        *(float4*)&buf[r * 64 + ((cb ^ (r >> 2)) & 15) * 4] =
            *(const float4*)&src[(size_t)r * stride + cb * 4];
    }
}
__device__ __forceinline__ void load_trans(float* buf, const float* src, int stride, int tid) {
    for (int e = tid; e < 1024; e += 256) {
        int i = e >> 4, c4 = (e & 15) * 4;
        float4 v = *(const float4*)&src[(size_t)i * stride + c4];
        stT1(buf, c4 + 0, i, v.x);
        stT1(buf, c4 + 1, i, v.y);
        stT1(buf, c4 + 2, i, v.z);
        stT1(buf, c4 + 3, i, v.w);
    }
}
template <bool SUB>
__device__ __forceinline__ void mm64(const float* A, const float* B,
                                     float (&acc)[4][4], int ty4, int tx4) {
#pragma unroll
    for (int cb = 0; cb < 16; cb++) {
        float4 a[4], b[4];
#pragma unroll
        for (int ii = 0; ii < 4; ii++) a[ii] = ldT4(A, ty4 + ii, cb);
#pragma unroll
        for (int jj = 0; jj < 4; jj++) b[jj] = ldT4(B, tx4 + jj, cb);
#pragma unroll
        for (int ii = 0; ii < 4; ii++)
#pragma unroll
            for (int jj = 0; jj < 4; jj++) {
                if (SUB) {
                    acc[ii][jj] = fmaf(-a[ii].x, b[jj].x, acc[ii][jj]);
                    acc[ii][jj] = fmaf(-a[ii].y, b[jj].y, acc[ii][jj]);
                    acc[ii][jj] = fmaf(-a[ii].z, b[jj].z, acc[ii][jj]);
                    acc[ii][jj] = fmaf(-a[ii].w, b[jj].w, acc[ii][jj]);
                } else {
                    acc[ii][jj] = fmaf(a[ii].x, b[jj].x, acc[ii][jj]);
                    acc[ii][jj] = fmaf(a[ii].y, b[jj].y, acc[ii][jj]);
                    acc[ii][jj] = fmaf(a[ii].z, b[jj].z, acc[ii][jj]);
                    acc[ii][jj] = fmaf(a[ii].w, b[jj].w, acc[ii][jj]);
                }
            }
    }
}

// ---------------------------------------------------------------------------
// 64x64 Cholesky factor + inverse -> g_Zd + W diag
// ---------------------------------------------------------------------------
__device__ void factor_inverse(Row* Lb, Row* Zb, int kout) {
    __shared__ float Mtmp[7 * 64];
    int tid = threadIdx.x, tx = tid % 16, ty = tid / 16;

    for (int e = tid; e < BS * BS; e += 256)
        Zb[e / BS][e % BS] = 0.f;
    __syncthreads();

    for (int j = 0; j < BS - 1; j++) {
        float inv = 1.f / Lb[j][j];
        for (int r = j + 1 + ty; r < BS; r += 16) {
            float lrj = Lb[r][j] * inv;
            for (int c = j + 1 + tx; c <= r; c += 16)
                Lb[r][c] -= lrj * Lb[c][j];
        }
        __syncthreads();
    }
    float vals[16];
    int q = 0;
    for (int e = tid; e < BS * BS; e += 256, q++) {
        int r = e / BS, c = e % BS;
        float v = Lb[r][c];
        if (c < r)       v *= rsqrtf(Lb[c][c]);
        else if (c == r) v = sqrtf(v);
        else             v = 0.f;
        vals[q] = v;
    }
    __syncthreads();
    q = 0;
    for (int e = tid; e < BS * BS; e += 256, q++)
        Lb[e / BS][e % BS] = vals[q];
    __syncthreads();

    if (tid < 64) {
        int g = tid >> 3, c = tid & 7, b0 = g * 8;
        Zb[b0 + c][b0 + c] = 1.f / Lb[b0 + c][b0 + c];
        for (int r = c + 1; r < 8; r++) {
            float s = 0.f;
            for (int k = c; k < r; k++)
                s += Lb[b0 + r][b0 + k] * Zb[b0 + k][b0 + c];
            Zb[b0 + r][b0 + c] = -s / Lb[b0 + r][b0 + r];
        }
    }
    __syncthreads();

    for (int bi = 1; bi < 8; bi++) {
        int tot = bi * 64;
        for (int e = tid; e < tot; e += 256) {
            int bj = e >> 6, rc = e & 63, r = rc >> 3, c = rc & 7;
            float s = 0.f;
            for (int k = bj * 8; k < bi * 8; k++)
                s += Lb[bi * 8 + r][k] * Zb[k][bj * 8 + c];
            Mtmp[e] = s;
        }
        __syncthreads();
        for (int e = tid; e < tot; e += 256) {
            int bj = e >> 6, rc = e & 63, r = rc >> 3, c = rc & 7;
            float s = 0.f;
#pragma unroll
            for (int t = 0; t < 8; t++)
                s += Zb[bi * 8 + r][bi * 8 + t] * Mtmp[bj * 64 + t * 8 + c];
            Zb[bi * 8 + r][bj * 8 + c] = -s;
        }
        __syncthreads();
    }

    for (int e = tid; e < BS * BS; e += 256) {
        int r = e / BS, c = e % BS;
        float v = Zb[r][c];
        g_Zd[kout * BS * BS + e] = v;
        g_W[(size_t)(kout * BS + r) * M_IND + kout * BS + c] = v;
    }
    __syncthreads();
}

// ---------------------------------------------------------------------------
// Kernel 1: prep + K_mm + Cholesky + dbl0 (C group) ; Shi/Slo (S group)
// ---------------------------------------------------------------------------
__global__ void __launch_bounds__(256, 1) fact_kernel(const float* __restrict__ xm,
                                                      const float* __restrict__ ls,
                                                      const float* __restrict__ sv,
                                                      const float* __restrict__ Xte) {
    extern __shared__ __align__(16) float sm[];
    float* SA = sm;
    float* SB = sm + TSTRIDE;
    float* SC = sm + 2 * TSTRIDE;
    Row* SAr = (Row*)SA;
    Row* SBr = (Row*)SB;
    __shared__ unsigned sh_a, sh_c;
    int tid = threadIdx.x, bid = blockIdx.x;
    if (tid == 0) { sh_a = g_epoch; sh_c = g_cepoch; }
    __syncthreads();
    unsigned s_all = sh_a, s_c = sh_c;
    const unsigned basec = s_c;

    int gthread = bid * 256 + tid;
    int tx = tid % 16, ty = tid / 16;
    int tx4 = tx * 4, ty4 = ty * 4;
    float svv = fabsf(sv[0]);

    // phase 1 (all): pre-scaled xm rows + norms; zero W (atomic-accum base)
    for (int m = gthread; m < M_IND; m += NBLK * 256) {
        float nrm = 0.f;
#pragma unroll
        for (int d = 0; d < D_DIM; d++) {
            float il = 1.f / (fabsf(ls[d]) + EPSV);
            float v = xm[m * D_DIM + d] * il;
            g_xs[m * D_DIM + d] = v;
            nrm += v * v;
        }
        g_nm[m] = nrm;
    }
    for (int e = gthread; e < M_IND * M_IND / 4; e += NBLK * 256)
        *(float4*)&g_W[e * 4] = make_float4(0.f, 0.f, 0.f, 0.f);
    bar_gen(&g_cnt, &g_epoch, NBLK, s_all);

    if (bid >= NC) {
        // ================= group S: build Shi/Slo, then exit =============
        float* Xs = SA;
        float* Ms = SB;
        int ntile = (SW / 64) * (M_IND / 32);
        for (int x = bid - NC; x < ntile; x += NBLK - NC) {
            int n0 = (x % (SW / 64)) * 64, m0 = (x / (SW / 64)) * 32;
            for (int e = tid; e < 64 * D_DIM; e += 256) {
                int i = e / D_DIM, d = e % D_DIM;
                int n = n0 + i;
                float il = 1.f / (fabsf(ls[d]) + EPSV);
                Xs[i * 17 + d] = (n < N_TE) ? Xte[n * D_DIM + d] * il : 0.f;
            }
            for (int e = tid; e < 32 * D_DIM; e += 256) {
                int i = e / D_DIM, d = e % D_DIM;
                Ms[i * 17 + d] = g_xs[(m0 + i) * D_DIM + d];
            }
            __syncthreads();

            int sx = tid % 64, sy = tid / 64;
            int n = n0 + sx;
            __align__(16) __nv_bfloat16 h8[8];
            __align__(16) __nv_bfloat16 l8[8];
#pragma unroll
            for (int mi = 0; mi < 8; mi++) {
                int ml = sy * 8 + mi;
                float outv = 0.f;
                if (n < N_TE) {
                    float d2 = 0.f;
#pragma unroll
                    for (int d = 0; d < D_DIM; d++) {
                        float diff = Xs[sx * 17 + d] - Ms[ml * 17 + d];
                        d2 += diff * diff;
                    }
                    outv = svv * fexp2n(d2 * NEG_HALF_LOG2E);
                }
                __nv_bfloat16 h = __float2bfloat16(outv);
                h8[mi] = h;
                l8[mi] = __float2bfloat16(outv - __bfloat162float(h));
            }
            size_t off = (size_t)n * M_IND + m0 + sy * 8;
            *(uint4*)&g_Shi[off] = *(uint4*)h8;
            *(uint4*)&g_Slo[off] = *(uint4*)l8;
            __syncthreads();
        }
        return;
    }

    // ================= group C: K_mm + Cholesky =================
    for (int x = bid; x < NB * (NB + 1) / 2; x += NC) {
        int br = 0;
        while ((br + 1) * (br + 2) / 2 <= x) br++;
        int bc = x - br * (br + 1) / 2;
        for (int e = tid; e < 64 * D_DIM; e += 256) {
            int i = e >> 4, d = e & 15;
            SAr[i][d] = g_xs[(br * 64 + i) * D_DIM + d];
            SBr[i][d] = g_xs[(bc * 64 + i) * D_DIM + d];
        }
        if (tid < 64) {
            SAr[tid][16] = g_nm[br * 64 + tid];
            SBr[tid][16] = g_nm[bc * 64 + tid];
        }
        __syncthreads();
        float dot[4][4] = {};
#pragma unroll
        for (int d = 0; d < D_DIM; d++) {
            float av[4], bv[4];
#pragma unroll
            for (int ii = 0; ii < 4; ii++) av[ii] = SAr[ty4 + ii][d];
#pragma unroll
            for (int jj = 0; jj < 4; jj++) bv[jj] = SBr[tx4 + jj][d];
#pragma unroll
            for (int ii = 0; ii < 4; ii++)
#pragma unroll
                for (int jj = 0; jj < 4; jj++) dot[ii][jj] += av[ii] * bv[jj];
        }
#pragma unroll
        for (int ii = 0; ii < 4; ii++) {
            int gr = br * 64 + ty4 + ii;
            float nr = SAr[ty4 + ii][16];
#pragma unroll
            for (int jj = 0; jj < 4; jj++) {
                int gc = bc * 64 + tx4 + jj;
                float d2 = fmaxf(nr + SBr[tx4 + jj][16] - 2.f * dot[ii][jj], 0.f);
                float v = svv * fexp2n(d2 * NEG_HALF_LOG2E);
                if (gr == gc) v += JITTER;
                g_L[(size_t)gr * M_IND + gc] = v;
            }
        }
        __syncthreads();
    }
    if (bid == 0) {
        for (int e = tid; e < BS * BS; e += 256)
            SAr[e / BS][e % BS] = g_L[(size_t)(e / BS) * M_IND + (e % BS)];
        __syncthreads();
        factor_inverse(SAr, SBr, 0);
    }
    bar_gen(&g_ccnt, &g_cepoch, NC, s_c);

    for (int k = 0; k < NB - 1; k++) {
        int o = k * BS, t = NB - 1 - k;
        unsigned target = basec + (unsigned)(k + 1);

        if (bid == 0) {
            int bi = k + 1;
            load_direct(SA, &g_L[(size_t)(bi * BS) * M_IND + o], M_IND, tid);
            load_direct(SB, &g_Zd[k * BS * BS], BS, tid);
            __syncthreads();
            float acc[4][4] = {};
            mm64<false>(SA, SB, acc, ty4, tx4);
#pragma unroll
            for (int ii = 0; ii < 4; ii++) {
                *(float4*)&g_L[(size_t)(bi * BS + ty4 + ii) * M_IND + o + tx4] =
                    make_float4(acc[ii][0], acc[ii][1], acc[ii][2], acc[ii][3]);
                *(float4*)&SC[(ty4 + ii) * 64 + ((tx ^ ((ty4 + ii) >> 2)) & 15) * 4] =
                    make_float4(acc[ii][0], acc[ii][1], acc[ii][2], acc[ii][3]);
            }
            __threadfence();
            __syncthreads();
            if (tid == 0) g_pflag[bi] = target;
            float u[4][4];
#pragma unroll
            for (int ii = 0; ii < 4; ii++) {
                float4 v = *(const float4*)&g_L[(size_t)(bi * BS + ty4 + ii) * M_IND + bi * BS + tx4];
                u[ii][0] = v.x; u[ii][1] = v.y; u[ii][2] = v.z; u[ii][3] = v.w;
            }
            mm64<true>(SC, SC, u, ty4, tx4);
            __syncthreads();
#pragma unroll
            for (int ii = 0; ii < 4; ii++)
#pragma unroll
                for (int jj = 0; jj < 4; jj++)
                    SAr[ty4 + ii][tx4 + jj] = u[ii][jj];
            factor_inverse(SAr, SBr, bi);
        } else {
            for (int p = bid - 1; p < t - 1; p += NC - 1) {
                int bi = k + 2 + p;
                load_direct(SA, &g_L[(size_t)(bi * BS) * M_IND + o], M_IND, tid);
                load_direct(SB, &g_Zd[k * BS * BS], BS, tid);
                __syncthreads();
                float acc[4][4] = {};
                mm64<false>(SA, SB, acc, ty4, tx4);
#pragma unroll
                for (int ii = 0; ii < 4; ii++)
                    *(float4*)&g_L[(size_t)(bi * BS + ty4 + ii) * M_IND + o + tx4] =
                        make_float4(acc[ii][0], acc[ii][1], acc[ii][2], acc[ii][3]);
                __threadfence();
                __syncthreads();
                if (tid == 0) g_pflag[bi] = target;
            }
            int ntile = t * (t + 1) / 2;
            for (int x = bid; x < ntile; x += NC - 1) {
                int r = 0;
                while ((r + 1) * (r + 2) / 2 <= x) r++;
                int c = x - r * (r + 1) / 2;
                int bi = k + 1 + r, bj = k + 1 + c;
                if (tid == 0) {
                    while (g_pflag[bi] < target) { }
                    while (g_pflag[bj] < target) { }
                    __threadfence();
                }
                __syncthreads();
                load_direct(SA, &g_L[(size_t)(bi * BS) * M_IND + o], M_IND, tid);
                load_direct(SB, &g_L[(size_t)(bj * BS) * M_IND + o], M_IND, tid);
                __syncthreads();
                float u[4][4];
#pragma unroll
                for (int ii = 0; ii < 4; ii++) {
                    float4 v = *(const float4*)&g_L[(size_t)(bi * BS + ty4 + ii) * M_IND + bj * BS + tx4];
                    u[ii][0] = v.x; u[ii][1] = v.y; u[ii][2] = v.z; u[ii][3] = v.w;
                }
                mm64<true>(SA, SB, u, ty4, tx4);
#pragma unroll
                for (int ii = 0; ii < 4; ii++)
                    *(float4*)&g_L[(size_t)(bi * BS + ty4 + ii) * M_IND + bj * BS + tx4] =
                        make_float4(u[ii][0], u[ii][1], u[ii][2], u[ii][3]);
                __syncthreads();
            }
        }
        bar_gen(&g_ccnt, &g_cepoch, NC, s_c);
    }

    // dbl0 (fused): CTAs 0..7, one pair each
    if (bid < 8) {
        int base = bid * 128;
        load_direct(SA, &g_L[(size_t)(base + 64) * M_IND + base], M_IND, tid);   // L21
        load_trans(SB, &g_W[(size_t)base * M_IND + base], M_IND, tid);           // W11^T
        __syncthreads();
        float acc[4][4] = {};
        mm64<false>(SA, SB, acc, ty4, tx4);
        __syncthreads();
#pragma unroll
        for (int ii = 0; ii < 4; ii++)
#pragma unroll
            for (int jj = 0; jj < 4; jj++)
                stT1(SC, tx4 + jj, ty4 + ii, acc[ii][jj]);
        __syncthreads();
        load_direct(SA, &g_W[(size_t)(base + 64) * M_IND + base + 64], M_IND, tid);  // W22
        __syncthreads();
        float ac2[4][4] = {};
        mm64<false>(SA, SC, ac2, ty4, tx4);
#pragma unroll
        for (int ii = 0; ii < 4; ii++)
            *(float4*)&g_W[(size_t)(base + 64 + ty4 + ii) * M_IND + base + tx4] =
                make_float4(-ac2[ii][0], -ac2[ii][1], -ac2[ii][2], -ac2[ii][3]);
    }
}

// ---------------------------------------------------------------------------
// Split-k doubling: one CTA per (pair, tile, k-chunk), atomic accumulation
// ---------------------------------------------------------------------------
__global__ void zero_tmp(int n4) {
    int e = blockIdx.x * 256 + threadIdx.x;
    if (e < n4) *(float4*)&g_tmp[e * 4] = make_float4(0.f, 0.f, 0.f, 0.f);
}

__global__ void __launch_bounds__(256, 1) dblA_kernel(int l) {
    extern __shared__ __align__(16) float sm[];
    float* SA = sm;
    float* SB = sm + TSTRIDE;
    int tid = threadIdx.x;
    int tx4 = (tid % 16) * 4, ty4 = (tid / 16) * 4;
    int s = 64 << l, tt = 1 << l;
    int TT = tt * (tt + 1) / 2;
    int x = blockIdx.x;
    int p = x / (tt * TT), rem = x % (tt * TT);
    int tr = rem / TT, y = rem % TT;
    int tc = 0;
    while (y >= tt - tc) { y -= tt - tc; tc++; }
    int k0 = (tc + y) * BS;
    int base = p * 2 * s;

    load_direct(SA, &g_L[(size_t)(base + s + tr * BS) * M_IND + base + k0], M_IND, tid);
    load_trans(SB, &g_W[(size_t)(base + k0) * M_IND + base + tc * BS], M_IND, tid);
    __syncthreads();
    float acc[4][4] = {};
    mm64<false>(SA, SB, acc, ty4, tx4);
#pragma unroll
    for (int ii = 0; ii < 4; ii++)
#pragma unroll
        for (int jj = 0; jj < 4; jj++)
            atomicAdd(&g_tmp[(size_t)p * s * s + (tr * BS + ty4 + ii) * s + tc * BS + tx4 + jj],
                      acc[ii][jj]);
}

__global__ void __launch_bounds__(256, 1) dblB_kernel(int l) {
    extern __shared__ __align__(16) float sm[];
    float* SA = sm;
    float* SB = sm + TSTRIDE;
    int tid = threadIdx.x;
    int tx4 = (tid % 16) * 4, ty4 = (tid / 16) * 4;
    int s = 64 << l, tt = 1 << l;
    int TT = tt * (tt + 1) / 2;
    int x = blockIdx.x;
    int p = x / (tt * TT), rem = x % (tt * TT);
    int tc = rem / TT, y = rem % TT;
    int tr = 0;
    while (y >= tr + 1) { y -= tr + 1; tr++; }
    int k0 = y * BS;
    int base = p * 2 * s;

    load_direct(SA, &g_W[(size_t)(base + s + tr * BS) * M_IND + base + s + k0], M_IND, tid);
    load_trans(SB, &g_tmp[(size_t)p * s * s + (size_t)k0 * s + tc * BS], s, tid);
    __syncthreads();
    float acc[4][4] = {};
    mm64<false>(SA, SB, acc, ty4, tx4);
#pragma unroll
    for (int ii = 0; ii < 4; ii++)
#pragma unroll
        for (int jj = 0; jj < 4; jj++)
            atomicAdd(&g_W[(size_t)(base + s + tr * BS + ty4 + ii) * M_IND + base + tc * BS + tx4 + jj],
                      -acc[ii][jj]);
}

// ---------------------------------------------------------------------------
// Final: bf16 split of W (upper blocks are zero already) + a1/a2
// ---------------------------------------------------------------------------
__global__ void final_kernel(const float* __restrict__ qu, const float* __restrict__ ch) {
    int gthread = blockIdx.x * 256 + threadIdx.x;
    int nth = gridDim.x * 256;
    for (int idx = gthread; idx < M_IND * M_IND; idx += nth) {
        float w = g_W[idx];
        __nv_bfloat16 h = __float2bfloat16(w);
        g_Whi[idx] = h;
        g_Wlo[idx] = __float2bfloat16(w - __bfloat162float(h));
    }
    int wid = gthread / 32, lane = threadIdx.x % 32, nw = nth / 32;
    for (int r = wid; r < M_IND; r += nw) {
        float s1 = 0.f, s2 = 0.f;
        for (int c = lane; c <= r; c += 32) {
            float w = g_W[(size_t)r * M_IND + c];
            s1 += w * qu[c];
            s2 += w * ch[c];
        }
#pragma unroll
        for (int off = 16; off; off >>= 1) {
            s1 += __shfl_down_sync(0xffffffff, s1, off);
            s2 += __shfl_down_sync(0xffffffff, s2, off);
        }
        if (lane == 0) { g_a1[r] = s1; g_a2[r] = s2; }
    }
}

// ---------------------------------------------------------------------------
// Warp-MMA bf16 GEMM + fused epilogue (round-5/6 proven)
// ---------------------------------------------------------------------------
#define STG_BYTES 65536
__global__ void __launch_bounds__(256) gemm_tc() {
    extern __shared__ __align__(1024) char dsm[];
    __shared__ float Rq[8][32], Rm[8][32], Rv[8][32];
    __shared__ float a1s[128], a2s[128];

    const uint32_t sbase = smem_to_u32(dsm);
    int tid = threadIdx.x, wid = tid >> 5, lane = tid & 31;
    int n0 = blockIdx.x * 128;
    int mb = 7 - (int)blockIdx.y;
    int m0 = mb * 128;
    int nchunks = (m0 + 128) >> 6;

    if (tid < 128) { a1s[tid] = g_a1[m0 + tid]; a2s[tid] = g_a2[m0 + tid]; }

    int wm = (wid >> 2) * 64;
    int wn = (wid & 3) * 32;
    int lrow16 = lane & 15, lhalf = lane >> 4;

    float acc[4][4][4];
#pragma unroll
    for (int i = 0; i < 4; i++)
#pragma unroll
        for (int j = 0; j < 4; j++)
#pragma unroll
            for (int r = 0; r < 4; r++) acc[i][j][r] = 0.f;

    for (int c = 0; c < nchunks + 1; c++) {
        if (c < nchunks) {
            int k0 = c << 6;
            uint32_t buf = sbase + (uint32_t)(c & 1) * STG_BYTES;
#pragma unroll
            for (int it = 0; it < 4; it++) {
                int e = tid + it * 256;
                int row = e >> 3, ch = e & 7;
                uint32_t soff = (uint32_t)(row * 128 + ((ch ^ (row & 7)) << 4));
                size_t wsrc = (size_t)(m0 + row) * M_IND + k0 + ch * 8;
                size_t ssrc = (size_t)(n0 + row) * M_IND + k0 + ch * 8;
                CPA(buf + soff,         &g_Whi[wsrc]);
                CPA(buf + 16384 + soff, &g_Wlo[wsrc]);
                CPA(buf + 32768 + soff, &g_Shi[ssrc]);
                CPA(buf + 49152 + soff, &g_Slo[ssrc]);
            }
            CPC();
        }
        if (c == 0) continue;

        if (c < nchunks) { CPW1(); } else { CPW0(); }
        __syncthreads();

        int cc = c - 1;
        uint32_t buf = sbase + (uint32_t)(cc & 1) * STG_BYTES;
        uint32_t WHIa = buf, WLOa = buf + 16384, SHIa = buf + 32768, SLOa = buf + 49152;

#pragma unroll
        for (int kk = 0; kk < 4; kk++) {
            uint32_t A[4][4], Bf[2][4];
#pragma unroll
            for (int j2 = 0; j2 < 2; j2++) {
                int row = wn + j2 * 16 + lrow16;
                int ch = kk * 2 + lhalf;
                LDSM4(Bf[j2], SHIa + (uint32_t)(row * 128 + ((ch ^ (row & 7)) << 4)));
            }
#pragma unroll
            for (int i = 0; i < 4; i++) {
                int row = wm + i * 16 + lrow16;
                int ch = kk * 2 + lhalf;
                LDSM4(A[i], WHIa + (uint32_t)(row * 128 + ((ch ^ (row & 7)) << 4)));
            }
#pragma unroll
            for (int i = 0; i < 4; i++)
#pragma unroll
                for (int j = 0; j < 4; j++)
                    MMA16816(acc[i][j], A[i], Bf[j >> 1][j & 1], Bf[j >> 1][(j & 1) + 2]);
#pragma unroll
            for (int j2 = 0; j2 < 2; j2++) {
                int row = wn + j2 * 16 + lrow16;
                int ch = kk * 2 + lhalf;
                LDSM4(Bf[j2], SLOa + (uint32_t)(row * 128 + ((ch ^ (row & 7)) << 4)));
            }
#pragma unroll
            for (int i = 0; i < 4; i++)
#pragma unroll
                for (int j = 0; j < 4; j++)
                    MMA16816(acc[i][j], A[i], Bf[j >> 1][j & 1], Bf[j >> 1][(j & 1) + 2]);
#pragma unroll
            for (int i = 0; i < 4; i++) {
                int row = wm + i * 16 + lrow16;
                int ch = kk * 2 + lhalf;
                LDSM4(A[i], WLOa + (uint32_t)(row * 128 + ((ch ^ (row & 7)) << 4)));
            }
#pragma unroll
            for (int j2 = 0; j2 < 2; j2++) {
                int row = wn + j2 * 16 + lrow16;
                int ch = kk * 2 + lhalf;
                LDSM4(Bf[j2], SHIa + (uint32_t)(row * 128 + ((ch ^ (row & 7)) << 4)));
            }
#pragma unroll
            for (int i = 0; i < 4; i++)
#pragma unroll
                for (int j = 0; j < 4; j++)
                    MMA16816(acc[i][j], A[i], Bf[j >> 1][j & 1], Bf[j >> 1][(j & 1) + 2]);
        }
        __syncthreads();
    }

    float a1r[8], a2r[8];
#pragma unroll
    for (int i = 0; i < 4; i++)
#pragma unroll
        for (int rh = 0; rh < 2; rh++) {
            int row = wm + i * 16 + (lane >> 2) + rh * 8;
            a1r[i * 2 + rh] = a1s[row];
            a2r[i * 2 + rh] = a2s[row];
        }

    float pq[8], pm[8], pv[8];
#pragma unroll
    for (int j = 0; j < 4; j++)
#pragma unroll
        for (int cbit = 0; cbit < 2; cbit++) {
            float q = 0.f, m = 0.f, v = 0.f;
#pragma unroll
            for (int i = 0; i < 4; i++)
#pragma unroll
                for (int rh = 0; rh < 2; rh++) {
                    float x = acc[i][j][rh * 2 + cbit];
                    q += x * x;
                    m += x * a1r[i * 2 + rh];
                    v += x * a2r[i * 2 + rh];
                }
            pq[j * 2 + cbit] = q; pm[j * 2 + cbit] = m; pv[j * 2 + cbit] = v;
        }
#pragma unroll
    for (int off = 4; off <= 16; off <<= 1)
#pragma unroll
        for (int s = 0; s < 8; s++) {
            pq[s] += __shfl_xor_sync(0xffffffff, pq[s], off);
            pm[s] += __shfl_xor_sync(0xffffffff, pm[s], off);
            pv[s] += __shfl_xor_sync(0xffffffff, pv[s], off);
        }
    if (lane < 4) {
#pragma unroll
        for (int j = 0; j < 4; j++)
#pragma unroll
            for (int cbit = 0; cbit < 2; cbit++) {
                int col = j * 8 + lane * 2 + cbit;
                Rq[wid][col] = pq[j * 2 + cbit];
                Rm[wid][col] = pm[j * 2 + cbit];
                Rv[wid][col] = pv[j * 2 + cbit];
            }
    }
    __syncthreads();
    if (tid < 128) {
        int n = tid;
        int w = n >> 5, cl = n & 31;
        g_q[mb * SW + n0 + n]  = Rq[w][cl] + Rq[w + 4][cl];
        g_mm[mb * SW + n0 + n] = Rm[w][cl] + Rm[w + 4][cl];
        g_vv[mb * SW + n0 + n] = Rv[w][cl] + Rv[w + 4][cl];
    }
}

// ---------------------------------------------------------------------------
__global__ void reduce_out(float* __restrict__ out, const float* __restrict__ sv) {
    int n = blockIdx.x * 256 + threadIdx.x;
    if (n >= N_TE) return;
    float q = 0.f, mm = 0.f, vv = 0.f;
#pragma unroll
    for (int mb = 0; mb < 8; mb++) {
        q  += g_q[mb * SW + n];
        mm += g_mm[mb * SW + n];
        vv += g_vv[mb * SW + n];
    }
    float svv = fabsf(sv[0]);
    out[n] = mm;
    out[N_TE + n] = svv - q + vv * vv;
}

// ---------------------------------------------------------------------------
extern "C" void kernel_launch(void* const* d_in, const int* in_sizes, int n_in,
                              void* d_out, int out_size) {
    const float* Xte = (const float*)d_in[0];
    const float* xm  = (const float*)d_in[1];
    const float* qu  = (const float*)d_in[2];
    const float* ch  = (const float*)d_in[3];
    const float* ls  = (const float*)d_in[4];
    const float* sv  = (const float*)d_in[5];
    float* out = (float*)d_out;

    static bool attr_done = false;
    if (!attr_done) {
        cudaFuncSetAttribute(gemm_tc, cudaFuncAttributeMaxDynamicSharedMemorySize,
                             2 * STG_BYTES);
        cudaFuncSetAttribute(fact_kernel, cudaFuncAttributeMaxDynamicSharedMemorySize,
                             FACT_SMEM);
        cudaFuncSetAttribute(dblA_kernel, cudaFuncAttributeMaxDynamicSharedMemorySize,
                             FACT_SMEM);
        cudaFuncSetAttribute(dblB_kernel, cudaFuncAttributeMaxDynamicSharedMemorySize,
                             FACT_SMEM);
        attr_done = true;
    }

    fact_kernel<<<NBLK, 256, FACT_SMEM>>>(xm, ls, sv, Xte);
    for (int l = 1; l < 4; l++) {
        int pairs = 8 >> l, tt = 1 << l;
        int s = 64 << l;
        int tot = pairs * tt * (tt * (tt + 1) / 2);
        int n4 = pairs * s * s / 4;
        zero_tmp<<<(n4 + 255) / 256, 256>>>(n4);
        dblA_kernel<<<tot, 256, FACT_SMEM>>>(l);
        dblB_kernel<<<tot, 256, FACT_SMEM>>>(l);
    }
    final_kernel<<<240, 256>>>(qu, ch);
    gemm_tc<<<dim3(SW / 128, 8), 256, 2 * STG_BYTES>>>();
    reduce_out<<<(N_TE + 255) / 256, 256>>>(out, sv);
}

// round 15
// speedup vs baseline: 1.1348x; 1.0107x over previous
#include <cuda_runtime.h>
#include <cuda_bf16.h>
#include <math.h>
#include <stdint.h>

// Problem constants (fixed by setup_inputs)
#define N_TE   20000
#define M_IND  1024
#define D_DIM  16
#define BS     64
#define NB     16
#define SW     20096          // 314*64 padded width
#define JITTER 1e-3f
#define EPSV   1e-9f
#define NBLK   120            // persistent grid
#define NC     48             // group C (factorization) CTAs

typedef float Row[BS + 1];
#define FACT_SMEM (3 * BS * (BS + 1) * 4)
#define TSTRIDE 4160

// ---- PTX helpers ----------------------------------------------------------
__device__ __forceinline__ uint32_t smem_to_u32(const void* p) {
    uint32_t a;
    asm("{ .reg .u64 t; cvta.to.shared.u64 t, %1; cvt.u32.u64 %0, t; }" : "=r"(a) : "l"(p));
    return a;
}
#define CPA(dst, src) \
    asm volatile("cp.async.cg.shared.global [%0], [%1], 16;" :: "r"(dst), "l"(src))
#define CPC() asm volatile("cp.async.commit_group;" ::: "memory")
#define CPW0() asm volatile("cp.async.wait_group 0;" ::: "memory")
#define CPW1() asm volatile("cp.async.wait_group 1;" ::: "memory")
#define LDSM4(R, addr) \
    asm volatile("ldmatrix.sync.aligned.m8n8.x4.shared.b16 {%0,%1,%2,%3}, [%4];" \
        : "=r"((R)[0]), "=r"((R)[1]), "=r"((R)[2]), "=r"((R)[3]) : "r"(addr))
#define MMA16816(acc, a, b0_, b1_) \
    asm volatile("mma.sync.aligned.m16n8k16.row.col.f32.bf16.bf16.f32 " \
        "{%0,%1,%2,%3}, {%4,%5,%6,%7}, {%8,%9}, {%0,%1,%2,%3};" \
        : "+f"((acc)[0]), "+f"((acc)[1]), "+f"((acc)[2]), "+f"((acc)[3]) \
        : "r"((a)[0]), "r"((a)[1]), "r"((a)[2]), "r"((a)[3]), "r"(b0_), "r"(b1_))

// ---- fast 2^y for y <= 0 --------------------------------------------------
__device__ __forceinline__ float fexp2n(float y) {
    y = fmaxf(y, -125.0f);
    float r = y + 12582912.0f;
    int n = __float_as_int(r) - 0x4B400000;
    float f = y - (r - 12582912.0f);
    float p = 1.540353e-4f;
    p = fmaf(p, f, 1.3333558e-3f);
    p = fmaf(p, f, 9.6181296e-3f);
    p = fmaf(p, f, 5.5504109e-2f);
    p = fmaf(p, f, 2.4022651e-1f);
    p = fmaf(p, f, 6.9314718e-1f);
    p = fmaf(p, f, 1.0f);
    return __int_as_float(__float_as_int(p) + (n << 23));
}
#define NEG_HALF_LOG2E (-0.72134752f)

// ---- scratch --------------------------------------------------------------
__device__ float g_L[M_IND * M_IND];
__device__ float g_W[M_IND * M_IND];
__device__ float g_Zd[NB * BS * BS];
__device__ float g_tmp[512 * 512];
__device__ float g_xs[M_IND * D_DIM];
__device__ float g_nm[M_IND];
__device__ float g_a1[M_IND];
__device__ float g_a2[M_IND];
__device__ float g_q[8 * SW];
__device__ float g_mm[8 * SW];
__device__ float g_vv[8 * SW];
__device__ __nv_bfloat16 g_Whi[M_IND * M_IND];
__device__ __nv_bfloat16 g_Wlo[M_IND * M_IND];
__device__ __nv_bfloat16 g_Shi[(size_t)SW * M_IND];
__device__ __nv_bfloat16 g_Slo[(size_t)SW * M_IND];
__device__ unsigned g_cnt = 0;
__device__ volatile unsigned g_epoch = 0;
__device__ unsigned g_ccnt = 0;
__device__ volatile unsigned g_cepoch = 0;
__device__ volatile unsigned g_pflag[NB];

// ---------------------------------------------------------------------------
__device__ __forceinline__ void bar_gen(unsigned* cnt, volatile unsigned* ep,
                                        unsigned n, unsigned& sense) {
    __syncthreads();
    if (threadIdx.x == 0) {
        unsigned target = sense + 1;
        __threadfence();
        if (atomicAdd(cnt, 1u) == n - 1) {
            atomicExch(cnt, 0u);
            __threadfence();
            *ep = target;
        } else {
            while (*ep < target) { }
            __threadfence();
        }
    }
    __syncthreads();
    sense += 1;
}

// ---- swizzled flat tiles + microkernel ------------------------------------
__device__ __forceinline__ float4 ldT4(const float* S, int r, int cb) {
    return *(const float4*)&S[r * 64 + (((cb) ^ (r >> 2)) & 15) * 4];
}
__device__ __forceinline__ void stT1(float* S, int r, int c, float v) {
    S[r * 64 + ((((c) >> 2) ^ (r >> 2)) & 15) * 4 + ((c) & 3)] = v;
}
__device__ __forceinline__ void load_direct(float* buf, const float* src, int stride, int tid) {
    for (int e = tid; e < 1024; e += 256) {
        int r = e >> 4, cb = e & 15;
        *(float4*)&buf[r * 64 + ((cb ^ (r >> 2)) & 15) * 4] =
            *(const float4*)&src[(size_t)r * stride + cb * 4];
    }
}
__device__ __forceinline__ void load_trans(float* buf, const float* src, int stride, int tid) {
    for (int e = tid; e < 1024; e += 256) {
        int i = e >> 4, c4 = (e & 15) * 4;
        float4 v = *(const float4*)&src[(size_t)i * stride + c4];
        stT1(buf, c4 + 0, i, v.x);
        stT1(buf, c4 + 1, i, v.y);
        stT1(buf, c4 + 2, i, v.z);
        stT1(buf, c4 + 3, i, v.w);
    }
}
template <bool SUB>
__device__ __forceinline__ void mm64(const float* A, const float* B,
                                     float (&acc)[4][4], int ty4, int tx4) {
#pragma unroll
    for (int cb = 0; cb < 16; cb++) {
        float4 a[4], b[4];
#pragma unroll
        for (int ii = 0; ii < 4; ii++) a[ii] = ldT4(A, ty4 + ii, cb);
#pragma unroll
        for (int jj = 0; jj < 4; jj++) b[jj] = ldT4(B, tx4 + jj, cb);
#pragma unroll
        for (int ii = 0; ii < 4; ii++)
#pragma unroll
            for (int jj = 0; jj < 4; jj++) {
                if (SUB) {
                    acc[ii][jj] = fmaf(-a[ii].x, b[jj].x, acc[ii][jj]);
                    acc[ii][jj] = fmaf(-a[ii].y, b[jj].y, acc[ii][jj]);
                    acc[ii][jj] = fmaf(-a[ii].z, b[jj].z, acc[ii][jj]);
                    acc[ii][jj] = fmaf(-a[ii].w, b[jj].w, acc[ii][jj]);
                } else {
                    acc[ii][jj] = fmaf(a[ii].x, b[jj].x, acc[ii][jj]);
                    acc[ii][jj] = fmaf(a[ii].y, b[jj].y, acc[ii][jj]);
                    acc[ii][jj] = fmaf(a[ii].z, b[jj].z, acc[ii][jj]);
                    acc[ii][jj] = fmaf(a[ii].w, b[jj].w, acc[ii][jj]);
                }
            }
    }
}

// ---------------------------------------------------------------------------
// 64x64 Cholesky factor + inverse -> g_Zd + W diag
// ---------------------------------------------------------------------------
__device__ void factor_inverse(Row* Lb, Row* Zb, int kout) {
    __shared__ float Mtmp[7 * 64];
    int tid = threadIdx.x, tx = tid % 16, ty = tid / 16;

    for (int e = tid; e < BS * BS; e += 256)
        Zb[e / BS][e % BS] = 0.f;
    __syncthreads();

    for (int j = 0; j < BS - 1; j++) {
        float inv = 1.f / Lb[j][j];
        for (int r = j + 1 + ty; r < BS; r += 16) {
            float lrj = Lb[r][j] * inv;
            for (int c = j + 1 + tx; c <= r; c += 16)
                Lb[r][c] -= lrj * Lb[c][j];
        }
        __syncthreads();
    }
    float vals[16];
    int q = 0;
    for (int e = tid; e < BS * BS; e += 256, q++) {
        int r = e / BS, c = e % BS;
        float v = Lb[r][c];
        if (c < r)       v *= rsqrtf(Lb[c][c]);
        else if (c == r) v = sqrtf(v);
        else             v = 0.f;
        vals[q] = v;
    }
    __syncthreads();
    q = 0;
    for (int e = tid; e < BS * BS; e += 256, q++)
        Lb[e / BS][e % BS] = vals[q];
    __syncthreads();

    if (tid < 64) {
        int g = tid >> 3, c = tid & 7, b0 = g * 8;
        Zb[b0 + c][b0 + c] = 1.f / Lb[b0 + c][b0 + c];
        for (int r = c + 1; r < 8; r++) {
            float s = 0.f;
            for (int k = c; k < r; k++)
                s += Lb[b0 + r][b0 + k] * Zb[b0 + k][b0 + c];
            Zb[b0 + r][b0 + c] = -s / Lb[b0 + r][b0 + r];
        }
    }
    __syncthreads();

    for (int bi = 1; bi < 8; bi++) {
        int tot = bi * 64;
        for (int e = tid; e < tot; e += 256) {
            int bj = e >> 6, rc = e & 63, r = rc >> 3, c = rc & 7;
            float s = 0.f;
            for (int k = bj * 8; k < bi * 8; k++)
                s += Lb[bi * 8 + r][k] * Zb[k][bj * 8 + c];
            Mtmp[e] = s;
        }
        __syncthreads();
        for (int e = tid; e < tot; e += 256) {
            int bj = e >> 6, rc = e & 63, r = rc >> 3, c = rc & 7;
            float s = 0.f;
#pragma unroll
            for (int t = 0; t < 8; t++)
                s += Zb[bi * 8 + r][bi * 8 + t] * Mtmp[bj * 64 + t * 8 + c];
            Zb[bi * 8 + r][bj * 8 + c] = -s;
        }
        __syncthreads();
    }

    for (int e = tid; e < BS * BS; e += 256) {
        int r = e / BS, c = e % BS;
        float v = Zb[r][c];
        g_Zd[kout * BS * BS + e] = v;
        g_W[(size_t)(kout * BS + r) * M_IND + kout * BS + c] = v;
    }
    __syncthreads();
}

// ---------------------------------------------------------------------------
// Kernel 1: prep + K_mm + Cholesky + dbl0 (C group) ; Shi/Slo (S group)
// ---------------------------------------------------------------------------
__global__ void __launch_bounds__(256, 1) fact_kernel(const float* __restrict__ xm,
                                                      const float* __restrict__ ls,
                                                      const float* __restrict__ sv,
                                                      const float* __restrict__ Xte) {
    extern __shared__ __align__(16) float sm[];
    float* SA = sm;
    float* SB = sm + TSTRIDE;
    float* SC = sm + 2 * TSTRIDE;
    Row* SAr = (Row*)SA;
    Row* SBr = (Row*)SB;
    __shared__ unsigned sh_a, sh_c;
    int tid = threadIdx.x, bid = blockIdx.x;
    if (tid == 0) { sh_a = g_epoch; sh_c = g_cepoch; }
    __syncthreads();
    unsigned s_all = sh_a, s_c = sh_c;
    const unsigned basec = s_c;

    int gthread = bid * 256 + tid;
    int tx = tid % 16, ty = tid / 16;
    int tx4 = tx * 4, ty4 = ty * 4;
    float svv = fabsf(sv[0]);

    // phase 1 (all): pre-scaled xm rows + norms; zero W (atomic-accum base)
    for (int m = gthread; m < M_IND; m += NBLK * 256) {
        float nrm = 0.f;
#pragma unroll
        for (int d = 0; d < D_DIM; d++) {
            float il = 1.f / (fabsf(ls[d]) + EPSV);
            float v = xm[m * D_DIM + d] * il;
            g_xs[m * D_DIM + d] = v;
            nrm += v * v;
        }
        g_nm[m] = nrm;
    }
    for (int e = gthread; e < M_IND * M_IND / 4; e += NBLK * 256)
        *(float4*)&g_W[e * 4] = make_float4(0.f, 0.f, 0.f, 0.f);
    bar_gen(&g_cnt, &g_epoch, NBLK, s_all);

    if (bid >= NC) {
        // ================= group S: build Shi/Slo, then exit =============
        float* Xs = SA;
        float* Ms = SB;
        int ntile = (SW / 64) * (M_IND / 32);
        for (int x = bid - NC; x < ntile; x += NBLK - NC) {
            int n0 = (x % (SW / 64)) * 64, m0 = (x / (SW / 64)) * 32;
            for (int e = tid; e < 64 * D_DIM; e += 256) {
                int i = e / D_DIM, d = e % D_DIM;
                int n = n0 + i;
                float il = 1.f / (fabsf(ls[d]) + EPSV);
                Xs[i * 17 + d] = (n < N_TE) ? Xte[n * D_DIM + d] * il : 0.f;
            }
            for (int e = tid; e < 32 * D_DIM; e += 256) {
                int i = e / D_DIM, d = e % D_DIM;
                Ms[i * 17 + d] = g_xs[(m0 + i) * D_DIM + d];
            }
            __syncthreads();

            int sx = tid % 64, sy = tid / 64;
            int n = n0 + sx;
            __align__(16) __nv_bfloat16 h8[8];
            __align__(16) __nv_bfloat16 l8[8];
#pragma unroll
            for (int mi = 0; mi < 8; mi++) {
                int ml = sy * 8 + mi;
                float outv = 0.f;
                if (n < N_TE) {
                    float d2 = 0.f;
#pragma unroll
                    for (int d = 0; d < D_DIM; d++) {
                        float diff = Xs[sx * 17 + d] - Ms[ml * 17 + d];
                        d2 += diff * diff;
                    }
                    outv = svv * fexp2n(d2 * NEG_HALF_LOG2E);
                }
                __nv_bfloat16 h = __float2bfloat16(outv);
                h8[mi] = h;
                l8[mi] = __float2bfloat16(outv - __bfloat162float(h));
            }
            size_t off = (size_t)n * M_IND + m0 + sy * 8;
            *(uint4*)&g_Shi[off] = *(uint4*)h8;
            *(uint4*)&g_Slo[off] = *(uint4*)l8;
            __syncthreads();
        }
        return;
    }

    // ================= group C: K_mm + Cholesky =================
    for (int x = bid; x < NB * (NB + 1) / 2; x += NC) {
        int br = 0;
        while ((br + 1) * (br + 2) / 2 <= x) br++;
        int bc = x - br * (br + 1) / 2;
        for (int e = tid; e < 64 * D_DIM; e += 256) {
            int i = e >> 4, d = e & 15;
            SAr[i][d] = g_xs[(br * 64 + i) * D_DIM + d];
            SBr[i][d] = g_xs[(bc * 64 + i) * D_DIM + d];
        }
        if (tid < 64) {
            SAr[tid][16] = g_nm[br * 64 + tid];
            SBr[tid][16] = g_nm[bc * 64 + tid];
        }
        __syncthreads();
        float dot[4][4] = {};
#pragma unroll
        for (int d = 0; d < D_DIM; d++) {
            float av[4], bv[4];
#pragma unroll
            for (int ii = 0; ii < 4; ii++) av[ii] = SAr[ty4 + ii][d];
#pragma unroll
            for (int jj = 0; jj < 4; jj++) bv[jj] = SBr[tx4 + jj][d];
#pragma unroll
            for (int ii = 0; ii < 4; ii++)
#pragma unroll
                for (int jj = 0; jj < 4; jj++) dot[ii][jj] += av[ii] * bv[jj];
        }
#pragma unroll
        for (int ii = 0; ii < 4; ii++) {
            int gr = br * 64 + ty4 + ii;
            float nr = SAr[ty4 + ii][16];
#pragma unroll
            for (int jj = 0; jj < 4; jj++) {
                int gc = bc * 64 + tx4 + jj;
                float d2 = fmaxf(nr + SBr[tx4 + jj][16] - 2.f * dot[ii][jj], 0.f);
                float v = svv * fexp2n(d2 * NEG_HALF_LOG2E);
                if (gr == gc) v += JITTER;
                g_L[(size_t)gr * M_IND + gc] = v;
            }
        }
        __syncthreads();
    }
    if (bid == 0) {
        for (int e = tid; e < BS * BS; e += 256)
            SAr[e / BS][e % BS] = g_L[(size_t)(e / BS) * M_IND + (e % BS)];
        __syncthreads();
        factor_inverse(SAr, SBr, 0);
    }
    bar_gen(&g_ccnt, &g_cepoch, NC, s_c);

    for (int k = 0; k < NB - 1; k++) {
        int o = k * BS, t = NB - 1 - k;
        unsigned target = basec + (unsigned)(k + 1);

        if (bid == 0) {
            int bi = k + 1;
            load_direct(SA, &g_L[(size_t)(bi * BS) * M_IND + o], M_IND, tid);
            load_direct(SB, &g_Zd[k * BS * BS], BS, tid);
            __syncthreads();
            // prefetch diag accumulator (independent of panel result)
            float u[4][4];
#pragma unroll
            for (int ii = 0; ii < 4; ii++) {
                float4 v = *(const float4*)&g_L[(size_t)(bi * BS + ty4 + ii) * M_IND + bi * BS + tx4];
                u[ii][0] = v.x; u[ii][1] = v.y; u[ii][2] = v.z; u[ii][3] = v.w;
            }
            float acc[4][4] = {};
            mm64<false>(SA, SB, acc, ty4, tx4);
#pragma unroll
            for (int ii = 0; ii < 4; ii++) {
                *(float4*)&g_L[(size_t)(bi * BS + ty4 + ii) * M_IND + o + tx4] =
                    make_float4(acc[ii][0], acc[ii][1], acc[ii][2], acc[ii][3]);
                *(float4*)&SC[(ty4 + ii) * 64 + ((tx ^ ((ty4 + ii) >> 2)) & 15) * 4] =
                    make_float4(acc[ii][0], acc[ii][1], acc[ii][2], acc[ii][3]);
            }
            __threadfence();
            __syncthreads();
            if (tid == 0) g_pflag[bi] = target;
            mm64<true>(SC, SC, u, ty4, tx4);
            __syncthreads();
#pragma unroll
            for (int ii = 0; ii < 4; ii++)
#pragma unroll
                for (int jj = 0; jj < 4; jj++)
                    SAr[ty4 + ii][tx4 + jj] = u[ii][jj];
            factor_inverse(SAr, SBr, bi);
        } else {
            // hoisted Zd load (only if this CTA owns any panel)
            if (bid - 1 < t - 1) {
                load_direct(SB, &g_Zd[k * BS * BS], BS, tid);
                for (int p = bid - 1; p < t - 1; p += NC - 1) {
                    int bi = k + 2 + p;
                    load_direct(SA, &g_L[(size_t)(bi * BS) * M_IND + o], M_IND, tid);
                    __syncthreads();
                    float acc[4][4] = {};
                    mm64<false>(SA, SB, acc, ty4, tx4);
#pragma unroll
                    for (int ii = 0; ii < 4; ii++)
                        *(float4*)&g_L[(size_t)(bi * BS + ty4 + ii) * M_IND + o + tx4] =
                            make_float4(acc[ii][0], acc[ii][1], acc[ii][2], acc[ii][3]);
                    __threadfence();
                    __syncthreads();
                    if (tid == 0) g_pflag[bi] = target;
                }
            }
            int ntile = t * (t + 1) / 2;
            for (int x = bid; x < ntile; x += NC - 1) {
                int r = 0;
                while ((r + 1) * (r + 2) / 2 <= x) r++;
                int c = x - r * (r + 1) / 2;
                int bi = k + 1 + r, bj = k + 1 + c;
                // prefetch accumulator (tile untouched this step) before flag wait
                float u[4][4];
#pragma unroll
                for (int ii = 0; ii < 4; ii++) {
                    float4 v = *(const float4*)&g_L[(size_t)(bi * BS + ty4 + ii) * M_IND + bj * BS + tx4];
                    u[ii][0] = v.x; u[ii][1] = v.y; u[ii][2] = v.z; u[ii][3] = v.w;
                }
                if (tid == 0) {
                    while (g_pflag[bi] < target) { }
                    while (g_pflag[bj] < target) { }
                    __threadfence();
                }
                __syncthreads();
                load_direct(SA, &g_L[(size_t)(bi * BS) * M_IND + o], M_IND, tid);
                load_direct(SB, &g_L[(size_t)(bj * BS) * M_IND + o], M_IND, tid);
                __syncthreads();
                mm64<true>(SA, SB, u, ty4, tx4);
#pragma unroll
                for (int ii = 0; ii < 4; ii++)
                    *(float4*)&g_L[(size_t)(bi * BS + ty4 + ii) * M_IND + bj * BS + tx4] =
                        make_float4(u[ii][0], u[ii][1], u[ii][2], u[ii][3]);
                __syncthreads();
            }
        }
        bar_gen(&g_ccnt, &g_cepoch, NC, s_c);
    }

    // dbl0 (fused): CTAs 0..7, one pair each
    if (bid < 8) {
        int base = bid * 128;
        load_direct(SA, &g_L[(size_t)(base + 64) * M_IND + base], M_IND, tid);   // L21
        load_trans(SB, &g_W[(size_t)base * M_IND + base], M_IND, tid);           // W11^T
        __syncthreads();
        float acc[4][4] = {};
        mm64<false>(SA, SB, acc, ty4, tx4);
        __syncthreads();
#pragma unroll
        for (int ii = 0; ii < 4; ii++)
#pragma unroll
            for (int jj = 0; jj < 4; jj++)
                stT1(SC, tx4 + jj, ty4 + ii, acc[ii][jj]);
        __syncthreads();
        load_direct(SA, &g_W[(size_t)(base + 64) * M_IND + base + 64], M_IND, tid);  // W22
        __syncthreads();
        float ac2[4][4] = {};
        mm64<false>(SA, SC, ac2, ty4, tx4);
#pragma unroll
        for (int ii = 0; ii < 4; ii++)
            *(float4*)&g_W[(size_t)(base + 64 + ty4 + ii) * M_IND + base + tx4] =
                make_float4(-ac2[ii][0], -ac2[ii][1], -ac2[ii][2], -ac2[ii][3]);
    }
}

// ---------------------------------------------------------------------------
// Split-k doubling: one CTA per (pair, tile, k-chunk), atomic accumulation
// ---------------------------------------------------------------------------
__global__ void __launch_bounds__(256, 2) zero_tmp(int n4) {
    int e = blockIdx.x * 256 + threadIdx.x;
    if (e < n4) *(float4*)&g_tmp[e * 4] = make_float4(0.f, 0.f, 0.f, 0.f);
}

__global__ void __launch_bounds__(256, 2) dblA_kernel(int l) {
    extern __shared__ __align__(16) float sm[];
    float* SA = sm;
    float* SB = sm + TSTRIDE;
    int tid = threadIdx.x;
    int tx4 = (tid % 16) * 4, ty4 = (tid / 16) * 4;
    int s = 64 << l, tt = 1 << l;
    int TT = tt * (tt + 1) / 2;
    int x = blockIdx.x;
    int p = x / (tt * TT), rem = x % (tt * TT);
    int tr = rem / TT, y = rem % TT;
    int tc = 0;
    while (y >= tt - tc) { y -= tt - tc; tc++; }
    int k0 = (tc + y) * BS;
    int base = p * 2 * s;

    load_direct(SA, &g_L[(size_t)(base + s + tr * BS) * M_IND + base + k0], M_IND, tid);
    load_trans(SB, &g_W[(size_t)(base + k0) * M_IND + base + tc * BS], M_IND, tid);
    __syncthreads();
    float acc[4][4] = {};
    mm64<false>(SA, SB, acc, ty4, tx4);
#pragma unroll
    for (int ii = 0; ii < 4; ii++)
#pragma unroll
        for (int jj = 0; jj < 4; jj++)
            atomicAdd(&g_tmp[(size_t)p * s * s + (tr * BS + ty4 + ii) * s + tc * BS + tx4 + jj],
                      acc[ii][jj]);
}

__global__ void __launch_bounds__(256, 2) dblB_kernel(int l) {
    extern __shared__ __align__(16) float sm[];
    float* SA = sm;
    float* SB = sm + TSTRIDE;
    int tid = threadIdx.x;
    int tx4 = (tid % 16) * 4, ty4 = (tid / 16) * 4;
    int s = 64 << l, tt = 1 << l;
    int TT = tt * (tt + 1) / 2;
    int x = blockIdx.x;
    int p = x / (tt * TT), rem = x % (tt * TT);
    int tc = rem / TT, y = rem % TT;
    int tr = 0;
    while (y >= tr + 1) { y -= tr + 1; tr++; }
    int k0 = y * BS;
    int base = p * 2 * s;

    load_direct(SA, &g_W[(size_t)(base + s + tr * BS) * M_IND + base + s + k0], M_IND, tid);
    load_trans(SB, &g_tmp[(size_t)p * s * s + (size_t)k0 * s + tc * BS], s, tid);
    __syncthreads();
    float acc[4][4] = {};
    mm64<false>(SA, SB, acc, ty4, tx4);
#pragma unroll
    for (int ii = 0; ii < 4; ii++)
#pragma unroll
        for (int jj = 0; jj < 4; jj++)
            atomicAdd(&g_W[(size_t)(base + s + tr * BS + ty4 + ii) * M_IND + base + tc * BS + tx4 + jj],
                      -acc[ii][jj]);
}

// ---------------------------------------------------------------------------
// Final: bf16 split of W (upper blocks are zero already) + a1/a2
// ---------------------------------------------------------------------------
__global__ void final_kernel(const float* __restrict__ qu, const float* __restrict__ ch) {
    int gthread = blockIdx.x * 256 + threadIdx.x;
    int nth = gridDim.x * 256;
    for (int idx = gthread; idx < M_IND * M_IND; idx += nth) {
        float w = g_W[idx];
        __nv_bfloat16 h = __float2bfloat16(w);
        g_Whi[idx] = h;
        g_Wlo[idx] = __float2bfloat16(w - __bfloat162float(h));
    }
    int wid = gthread / 32, lane = threadIdx.x % 32, nw = nth / 32;
    for (int r = wid; r < M_IND; r += nw) {
        float s1 = 0.f, s2 = 0.f;
        for (int c = lane; c <= r; c += 32) {
            float w = g_W[(size_t)r * M_IND + c];
            s1 += w * qu[c];
            s2 += w * ch[c];
        }
#pragma unroll
        for (int off = 16; off; off >>= 1) {
            s1 += __shfl_down_sync(0xffffffff, s1, off);
            s2 += __shfl_down_sync(0xffffffff, s2, off);
        }
        if (lane == 0) { g_a1[r] = s1; g_a2[r] = s2; }
    }
}

// ---------------------------------------------------------------------------
// Warp-MMA bf16 GEMM + fused epilogue (round-5/6 proven)
// ---------------------------------------------------------------------------
#define STG_BYTES 65536
__global__ void __launch_bounds__(256) gemm_tc() {
    extern __shared__ __align__(1024) char dsm[];
    __shared__ float Rq[8][32], Rm[8][32], Rv[8][32];
    __shared__ float a1s[128], a2s[128];

    const uint32_t sbase = smem_to_u32(dsm);
    int tid = threadIdx.x, wid = tid >> 5, lane = tid & 31;
    int n0 = blockIdx.x * 128;
    int mb = 7 - (int)blockIdx.y;
    int m0 = mb * 128;
    int nchunks = (m0 + 128) >> 6;

    if (tid < 128) { a1s[tid] = g_a1[m0 + tid]; a2s[tid] = g_a2[m0 + tid]; }

    int wm = (wid >> 2) * 64;
    int wn = (wid & 3) * 32;
    int lrow16 = lane & 15, lhalf = lane >> 4;

    float acc[4][4][4];
#pragma unroll
    for (int i = 0; i < 4; i++)
#pragma unroll
        for (int j = 0; j < 4; j++)
#pragma unroll
            for (int r = 0; r < 4; r++) acc[i][j][r] = 0.f;

    for (int c = 0; c < nchunks + 1; c++) {
        if (c < nchunks) {
            int k0 = c << 6;
            uint32_t buf = sbase + (uint32_t)(c & 1) * STG_BYTES;
#pragma unroll
            for (int it = 0; it < 4; it++) {
                int e = tid + it * 256;
                int row = e >> 3, ch = e & 7;
                uint32_t soff = (uint32_t)(row * 128 + ((ch ^ (row & 7)) << 4));
                size_t wsrc = (size_t)(m0 + row) * M_IND + k0 + ch * 8;
                size_t ssrc = (size_t)(n0 + row) * M_IND + k0 + ch * 8;
                CPA(buf + soff,         &g_Whi[wsrc]);
                CPA(buf + 16384 + soff, &g_Wlo[wsrc]);
                CPA(buf + 32768 + soff, &g_Shi[ssrc]);
                CPA(buf + 49152 + soff, &g_Slo[ssrc]);
            }
            CPC();
        }
        if (c == 0) continue;

        if (c < nchunks) { CPW1(); } else { CPW0(); }
        __syncthreads();

        int cc = c - 1;
        uint32_t buf = sbase + (uint32_t)(cc & 1) * STG_BYTES;
        uint32_t WHIa = buf, WLOa = buf + 16384, SHIa = buf + 32768, SLOa = buf + 49152;

#pragma unroll
        for (int kk = 0; kk < 4; kk++) {
            uint32_t A[4][4], Bf[2][4];
#pragma unroll
            for (int j2 = 0; j2 < 2; j2++) {
                int row = wn + j2 * 16 + lrow16;
                int ch = kk * 2 + lhalf;
                LDSM4(Bf[j2], SHIa + (uint32_t)(row * 128 + ((ch ^ (row & 7)) << 4)));
            }
#pragma unroll
            for (int i = 0; i < 4; i++) {
                int row = wm + i * 16 + lrow16;
                int ch = kk * 2 + lhalf;
                LDSM4(A[i], WHIa + (uint32_t)(row * 128 + ((ch ^ (row & 7)) << 4)));
            }
#pragma unroll
            for (int i = 0; i < 4; i++)
#pragma unroll
                for (int j = 0; j < 4; j++)
                    MMA16816(acc[i][j], A[i], Bf[j >> 1][j & 1], Bf[j >> 1][(j & 1) + 2]);
#pragma unroll
            for (int j2 = 0; j2 < 2; j2++) {
                int row = wn + j2 * 16 + lrow16;
                int ch = kk * 2 + lhalf;
                LDSM4(Bf[j2], SLOa + (uint32_t)(row * 128 + ((ch ^ (row & 7)) << 4)));
            }
#pragma unroll
            for (int i = 0; i < 4; i++)
#pragma unroll
                for (int j = 0; j < 4; j++)
                    MMA16816(acc[i][j], A[i], Bf[j >> 1][j & 1], Bf[j >> 1][(j & 1) + 2]);
#pragma unroll
            for (int i = 0; i < 4; i++) {
                int row = wm + i * 16 + lrow16;
                int ch = kk * 2 + lhalf;
                LDSM4(A[i], WLOa + (uint32_t)(row * 128 + ((ch ^ (row & 7)) << 4)));
            }
#pragma unroll
            for (int j2 = 0; j2 < 2; j2++) {
                int row = wn + j2 * 16 + lrow16;
                int ch = kk * 2 + lhalf;
                LDSM4(Bf[j2], SHIa + (uint32_t)(row * 128 + ((ch ^ (row & 7)) << 4)));
            }
#pragma unroll
            for (int i = 0; i < 4; i++)
#pragma unroll
                for (int j = 0; j < 4; j++)
                    MMA16816(acc[i][j], A[i], Bf[j >> 1][j & 1], Bf[j >> 1][(j & 1) + 2]);
        }
        __syncthreads();
    }

    float a1r[8], a2r[8];
#pragma unroll
    for (int i = 0; i < 4; i++)
#pragma unroll
        for (int rh = 0; rh < 2; rh++) {
            int row = wm + i * 16 + (lane >> 2) + rh * 8;
            a1r[i * 2 + rh] = a1s[row];
            a2r[i * 2 + rh] = a2s[row];
        }

    float pq[8], pm[8], pv[8];
#pragma unroll
    for (int j = 0; j < 4; j++)
#pragma unroll
        for (int cbit = 0; cbit < 2; cbit++) {
            float q = 0.f, m = 0.f, v = 0.f;
#pragma unroll
            for (int i = 0; i < 4; i++)
#pragma unroll
                for (int rh = 0; rh < 2; rh++) {
                    float x = acc[i][j][rh * 2 + cbit];
                    q += x * x;
                    m += x * a1r[i * 2 + rh];
                    v += x * a2r[i * 2 + rh];
                }
            pq[j * 2 + cbit] = q; pm[j * 2 + cbit] = m; pv[j * 2 + cbit] = v;
        }
#pragma unroll
    for (int off = 4; off <= 16; off <<= 1)
#pragma unroll
        for (int s = 0; s < 8; s++) {
            pq[s] += __shfl_xor_sync(0xffffffff, pq[s], off);
            pm[s] += __shfl_xor_sync(0xffffffff, pm[s], off);
            pv[s] += __shfl_xor_sync(0xffffffff, pv[s], off);
        }
    if (lane < 4) {
#pragma unroll
        for (int j = 0; j < 4; j++)
#pragma unroll
            for (int cbit = 0; cbit < 2; cbit++) {
                int col = j * 8 + lane * 2 + cbit;
                Rq[wid][col] = pq[j * 2 + cbit];
                Rm[wid][col] = pm[j * 2 + cbit];
                Rv[wid][col] = pv[j * 2 + cbit];
            }
    }
    __syncthreads();
    if (tid < 128) {
        int n = tid;
        int w = n >> 5, cl = n & 31;
        g_q[mb * SW + n0 + n]  = Rq[w][cl] + Rq[w + 4][cl];
        g_mm[mb * SW + n0 + n] = Rm[w][cl] + Rm[w + 4][cl];
        g_vv[mb * SW + n0 + n] = Rv[w][cl] + Rv[w + 4][cl];
    }
}

// ---------------------------------------------------------------------------
__global__ void reduce_out(float* __restrict__ out, const float* __restrict__ sv) {
    int n = blockIdx.x * 256 + threadIdx.x;
    if (n >= N_TE) return;
    float q = 0.f, mm = 0.f, vv = 0.f;
#pragma unroll
    for (int mb = 0; mb < 8; mb++) {
        q  += g_q[mb * SW + n];
        mm += g_mm[mb * SW + n];
        vv += g_vv[mb * SW + n];
    }
    float svv = fabsf(sv[0]);
    out[n] = mm;
    out[N_TE + n] = svv - q + vv * vv;
}

// ---------------------------------------------------------------------------
extern "C" void kernel_launch(void* const* d_in, const int* in_sizes, int n_in,
                              void* d_out, int out_size) {
    const float* Xte = (const float*)d_in[0];
    const float* xm  = (const float*)d_in[1];
    const float* qu  = (const float*)d_in[2];
    const float* ch  = (const float*)d_in[3];
    const float* ls  = (const float*)d_in[4];
    const float* sv  = (const float*)d_in[5];
    float* out = (float*)d_out;

    static bool attr_done = false;
    if (!attr_done) {
        cudaFuncSetAttribute(gemm_tc, cudaFuncAttributeMaxDynamicSharedMemorySize,
                             2 * STG_BYTES);
        cudaFuncSetAttribute(fact_kernel, cudaFuncAttributeMaxDynamicSharedMemorySize,
                             FACT_SMEM);
        cudaFuncSetAttribute(dblA_kernel, cudaFuncAttributeMaxDynamicSharedMemorySize,
                             FACT_SMEM);
        cudaFuncSetAttribute(dblB_kernel, cudaFuncAttributeMaxDynamicSharedMemorySize,
                             FACT_SMEM);
        attr_done = true;
    }

    fact_kernel<<<NBLK, 256, FACT_SMEM>>>(xm, ls, sv, Xte);
    for (int l = 1; l < 4; l++) {
        int pairs = 8 >> l, tt = 1 << l;
        int s = 64 << l;
        int tot = pairs * tt * (tt * (tt + 1) / 2);
        int n4 = pairs * s * s / 4;
        zero_tmp<<<(n4 + 255) / 256, 256>>>(n4);
        dblA_kernel<<<tot, 256, FACT_SMEM>>>(l);
        dblB_kernel<<<tot, 256, FACT_SMEM>>>(l);
    }
    final_kernel<<<240, 256>>>(qu, ch);
    gemm_tc<<<dim3(SW / 128, 8), 256, 2 * STG_BYTES>>>();
    reduce_out<<<(N_TE + 255) / 256, 256>>>(out, sv);
}